// round 1
// baseline (speedup 1.0000x reference)
#include <cuda_runtime.h>
#include <cstdint>

#define Bdim 8
#define Sdim 512
#define Hdim 768
#define Ldim 8192

// scratch (static device globals: allocation-free)
__device__ float g_attn_key[Bdim * Sdim * Hdim];                  // [B,S,H]  12.6 MB
__device__ float g_probs[(size_t)Bdim * Ldim * Sdim];             // [B,L,S]  134 MB
__device__ int   g_mask_is_i32;

// ---------------- PTX helpers ----------------
__device__ __forceinline__ uint32_t f2tf32(float x) {
    uint32_t r;
    asm("cvt.rna.tf32.f32 %0, %1;" : "=r"(r) : "f"(x));
    return r;
}

__device__ __forceinline__ void mma_m16n8k8(float* c, const uint32_t* a, const uint32_t* b) {
    asm volatile(
        "mma.sync.aligned.m16n8k8.row.col.f32.tf32.tf32.f32 "
        "{%0,%1,%2,%3}, {%4,%5,%6,%7}, {%8,%9}, {%0,%1,%2,%3};\n"
        : "+f"(c[0]), "+f"(c[1]), "+f"(c[2]), "+f"(c[3])
        : "r"(a[0]), "r"(a[1]), "r"(a[2]), "r"(a[3]), "r"(b[0]), "r"(b[1]));
}

__device__ __forceinline__ void cp16(uint32_t s, const void* g) {
    asm volatile("cp.async.cg.shared.global [%0], [%1], 16;\n" :: "r"(s), "l"(g));
}
__device__ __forceinline__ void cp_commit() { asm volatile("cp.async.commit_group;\n"); }
__device__ __forceinline__ void cp_wait1()  { asm volatile("cp.async.wait_group 1;\n"); }
__device__ __forceinline__ void cp_wait0()  { asm volatile("cp.async.wait_group 0;\n"); }

// ---------------- mask dtype detection ----------------
// bool masks may arrive as uint8 (numpy bool) or int32 (harness coercion).
// Scan first 1024 int32 words (= first 4096 bytes, safe under BOTH layouts:
// uint8 buffer is exactly 4096 B, int32 buffer is 16384 B). If all words are
// in {0,1} it is int32 (packed uint8 bools pass that test with prob ~8^-1024).
__global__ void k_detect(const int* __restrict__ m) {
    __shared__ int bad;
    if (threadIdx.x == 0) bad = 0;
    __syncthreads();
    int local = 0;
#pragma unroll
    for (int i = 0; i < 4; i++) {
        unsigned v = (unsigned)m[threadIdx.x + i * 256];
        if (v > 1u) local = 1;
    }
    if (local) atomicOr(&bad, 1);
    __syncthreads();
    if (threadIdx.x == 0) g_mask_is_i32 = bad ? 0 : 1;
}

// ---------------- Kernel 1: attn_key = inputs @ W_key^T ----------------
// C[4096,768] = A[4096,768(k)] x W[768(n),768(k)]   (NT: both k-contiguous)
// BM=128 BN=128 BK=32, 256 threads (warp grid 2x4, WM=64 WN=32)
__global__ __launch_bounds__(256) void k_keyproj(const float* __restrict__ A,
                                                 const float* __restrict__ W) {
    extern __shared__ __align__(16) float smem[];
    float* As = smem;                 // [2][128*36]
    float* Bs = smem + 2 * 128 * 36;  // [2][128*36] (n-major, k contig)
    uint32_t sb  = (uint32_t)__cvta_generic_to_shared(smem);
    const uint32_t sbA = sb;
    const uint32_t sbB = sb + 2u * 128u * 36u * 4u;

    const int tid  = threadIdx.x;
    const int lane = tid & 31, wid = tid >> 5;
    const int wm = wid & 1, wn = wid >> 1;
    const int tg = lane & 3, gid = lane >> 2;
    const int m0 = blockIdx.y * 128, n0 = blockIdx.x * 128;

    float acc[4][4][4];
#pragma unroll
    for (int i = 0; i < 4; i++)
#pragma unroll
        for (int j = 0; j < 4; j++)
#pragma unroll
            for (int r = 0; r < 4; r++) acc[i][j][r] = 0.f;

    // prologue: stage 0
#pragma unroll
    for (int i = 0; i < 4; i++) {
        int idx = tid + i * 256;
        int r = idx >> 3, c = (idx & 7) * 4;
        cp16(sbA + (uint32_t)(r * 36 + c) * 4u, A + (size_t)(m0 + r) * Hdim + c);
        cp16(sbB + (uint32_t)(r * 36 + c) * 4u, W + (size_t)(n0 + r) * Hdim + c);
    }
    cp_commit();

    const int KT = Hdim / 32;  // 24
#pragma unroll 1
    for (int kt = 0; kt < KT; ++kt) {
        int cur = kt & 1;
        if (kt + 1 < KT) {
            int nxt = cur ^ 1;
#pragma unroll
            for (int i = 0; i < 4; i++) {
                int idx = tid + i * 256;
                int r = idx >> 3, c = (idx & 7) * 4;
                cp16(sbA + (uint32_t)(nxt * 128 * 36 + r * 36 + c) * 4u,
                     A + (size_t)(m0 + r) * Hdim + (kt + 1) * 32 + c);
                cp16(sbB + (uint32_t)(nxt * 128 * 36 + r * 36 + c) * 4u,
                     W + (size_t)(n0 + r) * Hdim + (kt + 1) * 32 + c);
            }
            cp_commit();
            cp_wait1();
        } else {
            cp_wait0();
        }
        __syncthreads();
        const float* sA = As + cur * 128 * 36;
        const float* sB = Bs + cur * 128 * 36;
#pragma unroll
        for (int kk = 0; kk < 4; ++kk) {
            uint32_t af[4][4], bf[4][2];
#pragma unroll
            for (int mt = 0; mt < 4; ++mt) {
                int r = wm * 64 + mt * 16 + gid;
                af[mt][0] = f2tf32(sA[r * 36 + kk * 8 + tg]);
                af[mt][1] = f2tf32(sA[(r + 8) * 36 + kk * 8 + tg]);
                af[mt][2] = f2tf32(sA[r * 36 + kk * 8 + 4 + tg]);
                af[mt][3] = f2tf32(sA[(r + 8) * 36 + kk * 8 + 4 + tg]);
            }
#pragma unroll
            for (int nt = 0; nt < 4; ++nt) {
                int n = wn * 32 + nt * 8 + gid;
                bf[nt][0] = f2tf32(sB[n * 36 + kk * 8 + tg]);
                bf[nt][1] = f2tf32(sB[n * 36 + kk * 8 + 4 + tg]);
            }
#pragma unroll
            for (int mt = 0; mt < 4; ++mt)
#pragma unroll
                for (int nt = 0; nt < 4; ++nt)
                    mma_m16n8k8(acc[mt][nt], af[mt], bf[nt]);
        }
        __syncthreads();
    }
    // epilogue
#pragma unroll
    for (int mt = 0; mt < 4; ++mt) {
        int r = m0 + wm * 64 + mt * 16 + gid;
#pragma unroll
        for (int nt = 0; nt < 4; ++nt) {
            int c = n0 + wn * 32 + nt * 8 + tg * 2;
            *(float2*)(&g_attn_key[(size_t)r * Hdim + c]) =
                make_float2(acc[mt][nt][0], acc[mt][nt][1]);
            *(float2*)(&g_attn_key[(size_t)(r + 8) * Hdim + c]) =
                make_float2(acc[mt][nt][2], acc[mt][nt][3]);
        }
    }
}

// ---------------- Kernel 2: probs = softmax(mask(E @ attn_key[b]^T)) --------
// Per CTA: 64 labels x FULL S=512 (softmax needs the whole row).
// BM=64 BN=512 BK=16, 512 threads (warp grid 2x8, WM=32 WN=64)
#define K2_AS_FLOATS (2 * 64 * 20)
#define K2_BS_FLOATS (2 * 512 * 20)
#define K2_RED_FLOATS (64 * 8)
#define K2_SMEM_FLOATS (K2_AS_FLOATS + K2_BS_FLOATS + K2_RED_FLOATS)
#define K2_SMEM_BYTES (K2_SMEM_FLOATS * 4 + 512)

__global__ __launch_bounds__(512) void k_scores(const float* __restrict__ E,
                                                const void* __restrict__ masks) {
    extern __shared__ __align__(16) float smem[];
    float* As  = smem;
    float* Bs  = smem + K2_AS_FLOATS;
    float* red = smem + K2_AS_FLOATS + K2_BS_FLOATS;
    unsigned char* msk = (unsigned char*)(smem + K2_SMEM_FLOATS);
    uint32_t sb  = (uint32_t)__cvta_generic_to_shared(smem);
    const uint32_t sbA = sb;
    const uint32_t sbB = sb + (uint32_t)K2_AS_FLOATS * 4u;

    const int tid  = threadIdx.x;
    const int lane = tid & 31, wid = tid >> 5;
    const int wm = wid & 1, wn = wid >> 1;  // 2 x 8
    const int tg = lane & 3, gid = lane >> 2;
    const int b  = blockIdx.y;
    const int m0 = blockIdx.x * 64;
    const float* Bt = g_attn_key + (size_t)b * Sdim * Hdim;

    {   // mask -> smem (dtype-adaptive)
        int is32 = g_mask_is_i32;
        unsigned v = is32 ? (unsigned)((const int*)masks)[b * Sdim + tid]
                          : (unsigned)((const unsigned char*)masks)[b * Sdim + tid];
        msk[tid] = v ? 1 : 0;
    }

    float acc[2][8][4];
#pragma unroll
    for (int i = 0; i < 2; i++)
#pragma unroll
        for (int j = 0; j < 8; j++)
#pragma unroll
            for (int r = 0; r < 4; r++) acc[i][j][r] = 0.f;

    // prologue: stage 0
    if (tid < 256) {
        int r = tid >> 2, c = (tid & 3) * 4;
        cp16(sbA + (uint32_t)(r * 20 + c) * 4u, E + (size_t)(m0 + r) * Hdim + c);
    }
#pragma unroll
    for (int i = 0; i < 4; i++) {
        int idx = tid + i * 512;
        int r = idx >> 2, c = (idx & 3) * 4;
        cp16(sbB + (uint32_t)(r * 20 + c) * 4u, Bt + (size_t)r * Hdim + c);
    }
    cp_commit();

    const int KT = Hdim / 16;  // 48
#pragma unroll 1
    for (int kt = 0; kt < KT; ++kt) {
        int cur = kt & 1;
        if (kt + 1 < KT) {
            int nxt = cur ^ 1;
            if (tid < 256) {
                int r = tid >> 2, c = (tid & 3) * 4;
                cp16(sbA + (uint32_t)(nxt * 64 * 20 + r * 20 + c) * 4u,
                     E + (size_t)(m0 + r) * Hdim + (kt + 1) * 16 + c);
            }
#pragma unroll
            for (int i = 0; i < 4; i++) {
                int idx = tid + i * 512;
                int r = idx >> 2, c = (idx & 3) * 4;
                cp16(sbB + (uint32_t)(nxt * 512 * 20 + r * 20 + c) * 4u,
                     Bt + (size_t)r * Hdim + (kt + 1) * 16 + c);
            }
            cp_commit();
            cp_wait1();
        } else {
            cp_wait0();
        }
        __syncthreads();
        const float* sA = As + cur * 64 * 20;
        const float* sB = Bs + cur * 512 * 20;
#pragma unroll
        for (int kk = 0; kk < 2; ++kk) {
            uint32_t af[2][4], bf[8][2];
#pragma unroll
            for (int mt = 0; mt < 2; ++mt) {
                int r = wm * 32 + mt * 16 + gid;
                af[mt][0] = f2tf32(sA[r * 20 + kk * 8 + tg]);
                af[mt][1] = f2tf32(sA[(r + 8) * 20 + kk * 8 + tg]);
                af[mt][2] = f2tf32(sA[r * 20 + kk * 8 + 4 + tg]);
                af[mt][3] = f2tf32(sA[(r + 8) * 20 + kk * 8 + 4 + tg]);
            }
#pragma unroll
            for (int nt = 0; nt < 8; ++nt) {
                int n = wn * 64 + nt * 8 + gid;
                bf[nt][0] = f2tf32(sB[n * 20 + kk * 8 + tg]);
                bf[nt][1] = f2tf32(sB[n * 20 + kk * 8 + 4 + tg]);
            }
#pragma unroll
            for (int mt = 0; mt < 2; ++mt)
#pragma unroll
                for (int nt = 0; nt < 8; ++nt)
                    mma_m16n8k8(acc[mt][nt], af[mt], bf[nt]);
        }
        __syncthreads();
    }

    // ---- masked softmax epilogue ----
    // lane owns 4 rows: j = mt*2+p -> local row wm*32 + mt*16 + p*8 + gid
    float mx[4] = {-1e30f, -1e30f, -1e30f, -1e30f};
#pragma unroll
    for (int mt = 0; mt < 2; ++mt)
#pragma unroll
        for (int nt = 0; nt < 8; ++nt) {
            int col = wn * 64 + nt * 8 + tg * 2;
            bool m0ok = msk[col] != 0, m1ok = msk[col + 1] != 0;
            if (!m0ok) { acc[mt][nt][0] = -1e30f; acc[mt][nt][2] = -1e30f; }
            if (!m1ok) { acc[mt][nt][1] = -1e30f; acc[mt][nt][3] = -1e30f; }
            mx[mt * 2]     = fmaxf(mx[mt * 2],     fmaxf(acc[mt][nt][0], acc[mt][nt][1]));
            mx[mt * 2 + 1] = fmaxf(mx[mt * 2 + 1], fmaxf(acc[mt][nt][2], acc[mt][nt][3]));
        }
#pragma unroll
    for (int j = 0; j < 4; ++j) {
        mx[j] = fmaxf(mx[j], __shfl_xor_sync(0xffffffffu, mx[j], 1));
        mx[j] = fmaxf(mx[j], __shfl_xor_sync(0xffffffffu, mx[j], 2));
    }
    if (tg == 0) {
#pragma unroll
        for (int j = 0; j < 4; ++j) {
            int rl = wm * 32 + (j >> 1) * 16 + (j & 1) * 8 + gid;
            red[rl * 8 + wn] = mx[j];
        }
    }
    __syncthreads();
    float gmx[4];
#pragma unroll
    for (int j = 0; j < 4; ++j) {
        int rl = wm * 32 + (j >> 1) * 16 + (j & 1) * 8 + gid;
        float m = -1e30f;
#pragma unroll
        for (int w = 0; w < 8; ++w) m = fmaxf(m, red[rl * 8 + w]);
        gmx[j] = m;
    }
    __syncthreads();

    float sme[4] = {0.f, 0.f, 0.f, 0.f};
#pragma unroll
    for (int mt = 0; mt < 2; ++mt)
#pragma unroll
        for (int nt = 0; nt < 8; ++nt) {
            float e0 = __expf(acc[mt][nt][0] - gmx[mt * 2]);
            float e1 = __expf(acc[mt][nt][1] - gmx[mt * 2]);
            float e2 = __expf(acc[mt][nt][2] - gmx[mt * 2 + 1]);
            float e3 = __expf(acc[mt][nt][3] - gmx[mt * 2 + 1]);
            acc[mt][nt][0] = e0; acc[mt][nt][1] = e1;
            acc[mt][nt][2] = e2; acc[mt][nt][3] = e3;
            sme[mt * 2]     += e0 + e1;
            sme[mt * 2 + 1] += e2 + e3;
        }
#pragma unroll
    for (int j = 0; j < 4; ++j) {
        sme[j] += __shfl_xor_sync(0xffffffffu, sme[j], 1);
        sme[j] += __shfl_xor_sync(0xffffffffu, sme[j], 2);
    }
    if (tg == 0) {
#pragma unroll
        for (int j = 0; j < 4; ++j) {
            int rl = wm * 32 + (j >> 1) * 16 + (j & 1) * 8 + gid;
            red[rl * 8 + wn] = sme[j];
        }
    }
    __syncthreads();
    float inv[4];
#pragma unroll
    for (int j = 0; j < 4; ++j) {
        int rl = wm * 32 + (j >> 1) * 16 + (j & 1) * 8 + gid;
        float s = 0.f;
#pragma unroll
        for (int w = 0; w < 8; ++w) s += red[rl * 8 + w];
        inv[j] = 1.f / s;
    }

#pragma unroll
    for (int mt = 0; mt < 2; ++mt) {
        int r = m0 + wm * 32 + mt * 16 + gid;
        size_t base0 = ((size_t)b * Ldim + r) * Sdim;
        size_t base1 = ((size_t)b * Ldim + r + 8) * Sdim;
#pragma unroll
        for (int nt = 0; nt < 8; ++nt) {
            int col = wn * 64 + nt * 8 + tg * 2;
            *(float2*)(&g_probs[base0 + col]) =
                make_float2(acc[mt][nt][0] * inv[mt * 2], acc[mt][nt][1] * inv[mt * 2]);
            *(float2*)(&g_probs[base1 + col]) =
                make_float2(acc[mt][nt][2] * inv[mt * 2 + 1], acc[mt][nt][3] * inv[mt * 2 + 1]);
        }
    }
}

// ---------------- Kernel 3: out = probs @ inputs ----------------
// Per batch: C[8192,768] = P[8192,512(k)] x X[512(k),768(n)]   (NN)
// BM=128 BN=128 BK=32, 256 threads (warp grid 2x4)
__global__ __launch_bounds__(256) void k_out(const float* __restrict__ X,
                                             float* __restrict__ O) {
    extern __shared__ __align__(16) float smem[];
    float* As = smem;             // [2][128*36]
    float* Bs = smem + 2 * 128 * 36;  // [2][32*136] (k-major, n contig)
    uint32_t sb  = (uint32_t)__cvta_generic_to_shared(smem);
    const uint32_t sbA = sb;
    const uint32_t sbB = sb + 2u * 128u * 36u * 4u;

    const int tid  = threadIdx.x;
    const int lane = tid & 31, wid = tid >> 5;
    const int wm = wid & 1, wn = wid >> 1;
    const int tg = lane & 3, gid = lane >> 2;
    const int bb = blockIdx.z;
    const int m0 = blockIdx.y * 128, n0 = blockIdx.x * 128;
    const float* gA = g_probs + (size_t)bb * Ldim * Sdim;
    const float* gB = X + (size_t)bb * Sdim * Hdim;

    float acc[4][4][4];
#pragma unroll
    for (int i = 0; i < 4; i++)
#pragma unroll
        for (int j = 0; j < 4; j++)
#pragma unroll
            for (int r = 0; r < 4; r++) acc[i][j][r] = 0.f;

    // prologue: stage 0
#pragma unroll
    for (int i = 0; i < 4; i++) {
        int idx = tid + i * 256;
        int ra = idx >> 3, ca = (idx & 7) * 4;
        cp16(sbA + (uint32_t)(ra * 36 + ca) * 4u, gA + (size_t)(m0 + ra) * Sdim + ca);
        int rb = idx >> 5, cb = (idx & 31) * 4;
        cp16(sbB + (uint32_t)(rb * 136 + cb) * 4u, gB + (size_t)rb * Hdim + n0 + cb);
    }
    cp_commit();

    const int KT = Sdim / 32;  // 16
#pragma unroll 1
    for (int kt = 0; kt < KT; ++kt) {
        int cur = kt & 1;
        if (kt + 1 < KT) {
            int nxt = cur ^ 1;
#pragma unroll
            for (int i = 0; i < 4; i++) {
                int idx = tid + i * 256;
                int ra = idx >> 3, ca = (idx & 7) * 4;
                cp16(sbA + (uint32_t)(nxt * 128 * 36 + ra * 36 + ca) * 4u,
                     gA + (size_t)(m0 + ra) * Sdim + (kt + 1) * 32 + ca);
                int rb = idx >> 5, cb = (idx & 31) * 4;
                cp16(sbB + (uint32_t)(nxt * 32 * 136 + rb * 136 + cb) * 4u,
                     gB + (size_t)((kt + 1) * 32 + rb) * Hdim + n0 + cb);
            }
            cp_commit();
            cp_wait1();
        } else {
            cp_wait0();
        }
        __syncthreads();
        const float* sA = As + cur * 128 * 36;
        const float* sB = Bs + cur * 32 * 136;
#pragma unroll
        for (int kk = 0; kk < 4; ++kk) {
            uint32_t af[4][4], bf[4][2];
#pragma unroll
            for (int mt = 0; mt < 4; ++mt) {
                int r = wm * 64 + mt * 16 + gid;
                af[mt][0] = f2tf32(sA[r * 36 + kk * 8 + tg]);
                af[mt][1] = f2tf32(sA[(r + 8) * 36 + kk * 8 + tg]);
                af[mt][2] = f2tf32(sA[r * 36 + kk * 8 + 4 + tg]);
                af[mt][3] = f2tf32(sA[(r + 8) * 36 + kk * 8 + 4 + tg]);
            }
#pragma unroll
            for (int nt = 0; nt < 4; ++nt) {
                int n = wn * 32 + nt * 8 + gid;
                bf[nt][0] = f2tf32(sB[(kk * 8 + tg) * 136 + n]);
                bf[nt][1] = f2tf32(sB[(kk * 8 + 4 + tg) * 136 + n]);
            }
#pragma unroll
            for (int mt = 0; mt < 4; ++mt)
#pragma unroll
                for (int nt = 0; nt < 4; ++nt)
                    mma_m16n8k8(acc[mt][nt], af[mt], bf[nt]);
        }
        __syncthreads();
    }
    // epilogue -> out[b, l, h]
#pragma unroll
    for (int mt = 0; mt < 4; ++mt) {
        int r = m0 + wm * 64 + mt * 16 + gid;
        size_t base0 = (size_t)bb * Ldim * Hdim + (size_t)r * Hdim;
        size_t base1 = (size_t)bb * Ldim * Hdim + (size_t)(r + 8) * Hdim;
#pragma unroll
        for (int nt = 0; nt < 4; ++nt) {
            int c = n0 + wn * 32 + nt * 8 + tg * 2;
            *(float2*)(&O[base0 + c]) = make_float2(acc[mt][nt][0], acc[mt][nt][1]);
            *(float2*)(&O[base1 + c]) = make_float2(acc[mt][nt][2], acc[mt][nt][3]);
        }
    }
}

// ---------------- launcher ----------------
extern "C" void kernel_launch(void* const* d_in, const int* in_sizes, int n_in,
                              void* d_out, int out_size) {
    const float* inputs = (const float*)d_in[0];
    const void*  masks  = d_in[1];
    const float* emb    = (const float*)d_in[2];
    const float* wkey   = (const float*)d_in[3];
    float* out = (float*)d_out;
    (void)in_sizes; (void)n_in; (void)out_size;

    cudaFuncSetAttribute(k_keyproj, cudaFuncAttributeMaxDynamicSharedMemorySize, 73728);
    cudaFuncSetAttribute(k_scores,  cudaFuncAttributeMaxDynamicSharedMemorySize, K2_SMEM_BYTES);
    cudaFuncSetAttribute(k_out,     cudaFuncAttributeMaxDynamicSharedMemorySize, 71680);

    k_detect<<<1, 256>>>((const int*)masks);
    k_keyproj<<<dim3(6, 32, 1), 256, 73728>>>(inputs, wkey);
    k_scores<<<dim3(Ldim / 64, Bdim, 1), 512, K2_SMEM_BYTES>>>(emb, masks);
    k_out<<<dim3(6, Ldim / 128, Bdim), 256, 71680>>>(inputs, out);
}

// round 2
// speedup vs baseline: 1.1776x; 1.1776x over previous
#include <cuda_runtime.h>
#include <cstdint>

#define Bdim 8
#define Sdim 512
#define Hdim 768
#define Ldim 8192

// scratch (static device globals: allocation-free)
__device__ float g_attn_key[Bdim * Sdim * Hdim];                  // [B,S,H]  12.6 MB (tf32-rounded)
__device__ float g_probs[(size_t)Bdim * Ldim * Sdim];             // [B,L,S]  134 MB (tf32-rounded)
__device__ float g_xr[Bdim * Sdim * Hdim];                        // inputs, tf32-rounded
__device__ float g_er[Ldim * Hdim];                               // label_embedding, tf32-rounded
__device__ float g_wr[Hdim * Hdim];                               // W_key, tf32-rounded
__device__ int   g_mask_is_i32;

// ---------------- PTX helpers ----------------
__device__ __forceinline__ float round_tf32(float x) {
    uint32_t r;
    asm("cvt.rna.tf32.f32 %0, %1;" : "=r"(r) : "f"(x));
    return __uint_as_float(r);
}

__device__ __forceinline__ void mma_m16n8k8(float* c, const uint32_t* a, const uint32_t* b) {
    asm volatile(
        "mma.sync.aligned.m16n8k8.row.col.f32.tf32.tf32.f32 "
        "{%0,%1,%2,%3}, {%4,%5,%6,%7}, {%8,%9}, {%0,%1,%2,%3};\n"
        : "+f"(c[0]), "+f"(c[1]), "+f"(c[2]), "+f"(c[3])
        : "r"(a[0]), "r"(a[1]), "r"(a[2]), "r"(a[3]), "r"(b[0]), "r"(b[1]));
}

__device__ __forceinline__ void cp16(uint32_t s, const void* g) {
    asm volatile("cp.async.cg.shared.global [%0], [%1], 16;\n" :: "r"(s), "l"(g));
}
__device__ __forceinline__ void cp_commit() { asm volatile("cp.async.commit_group;\n"); }
__device__ __forceinline__ void cp_wait1()  { asm volatile("cp.async.wait_group 1;\n"); }
__device__ __forceinline__ void cp_wait0()  { asm volatile("cp.async.wait_group 0;\n"); }

// ---------------- prep: round arrays to tf32 once ----------------
__global__ void k_round(const float4* __restrict__ src, float4* __restrict__ dst, int n4) {
    int i = blockIdx.x * blockDim.x + threadIdx.x;
    int stride = gridDim.x * blockDim.x;
    for (; i < n4; i += stride) {
        float4 v = src[i];
        v.x = round_tf32(v.x); v.y = round_tf32(v.y);
        v.z = round_tf32(v.z); v.w = round_tf32(v.w);
        dst[i] = v;
    }
}

// ---------------- mask dtype detection ----------------
__global__ void k_detect(const int* __restrict__ m) {
    __shared__ int bad;
    if (threadIdx.x == 0) bad = 0;
    __syncthreads();
    int local = 0;
#pragma unroll
    for (int i = 0; i < 4; i++) {
        unsigned v = (unsigned)m[threadIdx.x + i * 256];
        if (v > 1u) local = 1;
    }
    if (local) atomicOr(&bad, 1);
    __syncthreads();
    if (threadIdx.x == 0) g_mask_is_i32 = bad ? 0 : 1;
}

// ---------------- Kernel 1: attn_key = inputs @ W_key^T ----------------
// C[4096,768] = A[4096,768(k)] x W[768(n),768(k)]   (NT, operands pre-rounded)
__global__ __launch_bounds__(256) void k_keyproj(const float* __restrict__ A,
                                                 const float* __restrict__ W) {
    extern __shared__ __align__(16) float smem[];
    float* As = smem;
    float* Bs = smem + 2 * 128 * 36;
    uint32_t sb  = (uint32_t)__cvta_generic_to_shared(smem);
    const uint32_t sbA = sb;
    const uint32_t sbB = sb + 2u * 128u * 36u * 4u;

    const int tid  = threadIdx.x;
    const int lane = tid & 31, wid = tid >> 5;
    const int wm = wid & 1, wn = wid >> 1;
    const int tg = lane & 3, gid = lane >> 2;
    const int m0 = blockIdx.y * 128, n0 = blockIdx.x * 128;

    float acc[4][4][4];
#pragma unroll
    for (int i = 0; i < 4; i++)
#pragma unroll
        for (int j = 0; j < 4; j++)
#pragma unroll
            for (int r = 0; r < 4; r++) acc[i][j][r] = 0.f;

#pragma unroll
    for (int i = 0; i < 4; i++) {
        int idx = tid + i * 256;
        int r = idx >> 3, c = (idx & 7) * 4;
        cp16(sbA + (uint32_t)(r * 36 + c) * 4u, A + (size_t)(m0 + r) * Hdim + c);
        cp16(sbB + (uint32_t)(r * 36 + c) * 4u, W + (size_t)(n0 + r) * Hdim + c);
    }
    cp_commit();

    const int KT = Hdim / 32;
#pragma unroll 1
    for (int kt = 0; kt < KT; ++kt) {
        int cur = kt & 1;
        if (kt + 1 < KT) {
            int nxt = cur ^ 1;
#pragma unroll
            for (int i = 0; i < 4; i++) {
                int idx = tid + i * 256;
                int r = idx >> 3, c = (idx & 7) * 4;
                cp16(sbA + (uint32_t)(nxt * 128 * 36 + r * 36 + c) * 4u,
                     A + (size_t)(m0 + r) * Hdim + (kt + 1) * 32 + c);
                cp16(sbB + (uint32_t)(nxt * 128 * 36 + r * 36 + c) * 4u,
                     W + (size_t)(n0 + r) * Hdim + (kt + 1) * 32 + c);
            }
            cp_commit();
            cp_wait1();
        } else {
            cp_wait0();
        }
        __syncthreads();
        const float* sA = As + cur * 128 * 36;
        const float* sB = Bs + cur * 128 * 36;
#pragma unroll
        for (int kk = 0; kk < 4; ++kk) {
            uint32_t af[4][4], bf[4][2];
#pragma unroll
            for (int mt = 0; mt < 4; ++mt) {
                int r = wm * 64 + mt * 16 + gid;
                af[mt][0] = __float_as_uint(sA[r * 36 + kk * 8 + tg]);
                af[mt][1] = __float_as_uint(sA[(r + 8) * 36 + kk * 8 + tg]);
                af[mt][2] = __float_as_uint(sA[r * 36 + kk * 8 + 4 + tg]);
                af[mt][3] = __float_as_uint(sA[(r + 8) * 36 + kk * 8 + 4 + tg]);
            }
#pragma unroll
            for (int nt = 0; nt < 4; ++nt) {
                int n = wn * 32 + nt * 8 + gid;
                bf[nt][0] = __float_as_uint(sB[n * 36 + kk * 8 + tg]);
                bf[nt][1] = __float_as_uint(sB[n * 36 + kk * 8 + 4 + tg]);
            }
#pragma unroll
            for (int mt = 0; mt < 4; ++mt)
#pragma unroll
                for (int nt = 0; nt < 4; ++nt)
                    mma_m16n8k8(acc[mt][nt], af[mt], bf[nt]);
        }
        __syncthreads();
    }
    // epilogue: store tf32-rounded attn_key (so k2 needs no cvt)
#pragma unroll
    for (int mt = 0; mt < 4; ++mt) {
        int r = m0 + wm * 64 + mt * 16 + gid;
#pragma unroll
        for (int nt = 0; nt < 4; ++nt) {
            int c = n0 + wn * 32 + nt * 8 + tg * 2;
            *(float2*)(&g_attn_key[(size_t)r * Hdim + c]) =
                make_float2(round_tf32(acc[mt][nt][0]), round_tf32(acc[mt][nt][1]));
            *(float2*)(&g_attn_key[(size_t)(r + 8) * Hdim + c]) =
                make_float2(round_tf32(acc[mt][nt][2]), round_tf32(acc[mt][nt][3]));
        }
    }
}

// ---------------- Kernel 2: probs = softmax(mask(E @ attn_key[b]^T)) --------
// BM=64 BN=512 BK=32, 512 threads (warp grid 2x8, WM=32 WN=64)
#define K2_AS_FLOATS (2 * 64 * 36)
#define K2_BS_FLOATS (2 * 512 * 36)
#define K2_RED_FLOATS (64 * 8)
#define K2_SMEM_FLOATS (K2_AS_FLOATS + K2_BS_FLOATS + K2_RED_FLOATS)
#define K2_SMEM_BYTES (K2_SMEM_FLOATS * 4 + 512)

__global__ __launch_bounds__(512) void k_scores(const float* __restrict__ E,
                                                const void* __restrict__ masks) {
    extern __shared__ __align__(16) float smem[];
    float* As  = smem;
    float* Bs  = smem + K2_AS_FLOATS;
    float* red = smem + K2_AS_FLOATS + K2_BS_FLOATS;
    unsigned char* msk = (unsigned char*)(smem + K2_SMEM_FLOATS);
    uint32_t sb  = (uint32_t)__cvta_generic_to_shared(smem);
    const uint32_t sbA = sb;
    const uint32_t sbB = sb + (uint32_t)K2_AS_FLOATS * 4u;

    const int tid  = threadIdx.x;
    const int lane = tid & 31, wid = tid >> 5;
    const int wm = wid & 1, wn = wid >> 1;  // 2 x 8
    const int tg = lane & 3, gid = lane >> 2;
    const int b  = blockIdx.y;
    const int m0 = blockIdx.x * 64;
    const float* Bt = g_attn_key + (size_t)b * Sdim * Hdim;

    {   // mask -> smem (dtype-adaptive)
        int is32 = g_mask_is_i32;
        unsigned v = is32 ? (unsigned)((const int*)masks)[b * Sdim + tid]
                          : (unsigned)((const unsigned char*)masks)[b * Sdim + tid];
        msk[tid] = v ? 1 : 0;
    }

    float acc[2][8][4];
#pragma unroll
    for (int i = 0; i < 2; i++)
#pragma unroll
        for (int j = 0; j < 8; j++)
#pragma unroll
            for (int r = 0; r < 4; r++) acc[i][j][r] = 0.f;

    // prologue: stage 0 (BK=32: A 64x32 -> 512 cp16, B 512x32 -> 4096 cp16)
    {
        int r = tid >> 3, c = (tid & 7) * 4;
        cp16(sbA + (uint32_t)(r * 36 + c) * 4u, E + (size_t)(m0 + r) * Hdim + c);
    }
#pragma unroll
    for (int i = 0; i < 8; i++) {
        int idx = tid + i * 512;
        int r = idx >> 3, c = (idx & 7) * 4;
        cp16(sbB + (uint32_t)(r * 36 + c) * 4u, Bt + (size_t)r * Hdim + c);
    }
    cp_commit();

    const int KT = Hdim / 32;  // 24
#pragma unroll 1
    for (int kt = 0; kt < KT; ++kt) {
        int cur = kt & 1;
        if (kt + 1 < KT) {
            int nxt = cur ^ 1;
            {
                int r = tid >> 3, c = (tid & 7) * 4;
                cp16(sbA + (uint32_t)(nxt * 64 * 36 + r * 36 + c) * 4u,
                     E + (size_t)(m0 + r) * Hdim + (kt + 1) * 32 + c);
            }
#pragma unroll
            for (int i = 0; i < 8; i++) {
                int idx = tid + i * 512;
                int r = idx >> 3, c = (idx & 7) * 4;
                cp16(sbB + (uint32_t)(nxt * 512 * 36 + r * 36 + c) * 4u,
                     Bt + (size_t)r * Hdim + (kt + 1) * 32 + c);
            }
            cp_commit();
            cp_wait1();
        } else {
            cp_wait0();
        }
        __syncthreads();
        const float* sA = As + cur * 64 * 36;
        const float* sB = Bs + cur * 512 * 36;
#pragma unroll
        for (int kk = 0; kk < 4; ++kk) {
            uint32_t af[2][4], bf[8][2];
#pragma unroll
            for (int mt = 0; mt < 2; ++mt) {
                int r = wm * 32 + mt * 16 + gid;
                af[mt][0] = __float_as_uint(sA[r * 36 + kk * 8 + tg]);
                af[mt][1] = __float_as_uint(sA[(r + 8) * 36 + kk * 8 + tg]);
                af[mt][2] = __float_as_uint(sA[r * 36 + kk * 8 + 4 + tg]);
                af[mt][3] = __float_as_uint(sA[(r + 8) * 36 + kk * 8 + 4 + tg]);
            }
#pragma unroll
            for (int nt = 0; nt < 8; ++nt) {
                int n = wn * 64 + nt * 8 + gid;
                bf[nt][0] = __float_as_uint(sB[n * 36 + kk * 8 + tg]);
                bf[nt][1] = __float_as_uint(sB[n * 36 + kk * 8 + 4 + tg]);
            }
#pragma unroll
            for (int mt = 0; mt < 2; ++mt)
#pragma unroll
                for (int nt = 0; nt < 8; ++nt)
                    mma_m16n8k8(acc[mt][nt], af[mt], bf[nt]);
        }
        __syncthreads();
    }

    // ---- masked softmax epilogue ----
    float mx[4] = {-1e30f, -1e30f, -1e30f, -1e30f};
#pragma unroll
    for (int mt = 0; mt < 2; ++mt)
#pragma unroll
        for (int nt = 0; nt < 8; ++nt) {
            int col = wn * 64 + nt * 8 + tg * 2;
            bool m0ok = msk[col] != 0, m1ok = msk[col + 1] != 0;
            if (!m0ok) { acc[mt][nt][0] = -1e30f; acc[mt][nt][2] = -1e30f; }
            if (!m1ok) { acc[mt][nt][1] = -1e30f; acc[mt][nt][3] = -1e30f; }
            mx[mt * 2]     = fmaxf(mx[mt * 2],     fmaxf(acc[mt][nt][0], acc[mt][nt][1]));
            mx[mt * 2 + 1] = fmaxf(mx[mt * 2 + 1], fmaxf(acc[mt][nt][2], acc[mt][nt][3]));
        }
#pragma unroll
    for (int j = 0; j < 4; ++j) {
        mx[j] = fmaxf(mx[j], __shfl_xor_sync(0xffffffffu, mx[j], 1));
        mx[j] = fmaxf(mx[j], __shfl_xor_sync(0xffffffffu, mx[j], 2));
    }
    if (tg == 0) {
#pragma unroll
        for (int j = 0; j < 4; ++j) {
            int rl = wm * 32 + (j >> 1) * 16 + (j & 1) * 8 + gid;
            red[rl * 8 + wn] = mx[j];
        }
    }
    __syncthreads();
    float gmx[4];
#pragma unroll
    for (int j = 0; j < 4; ++j) {
        int rl = wm * 32 + (j >> 1) * 16 + (j & 1) * 8 + gid;
        float m = -1e30f;
#pragma unroll
        for (int w = 0; w < 8; ++w) m = fmaxf(m, red[rl * 8 + w]);
        gmx[j] = m;
    }
    __syncthreads();

    float sme[4] = {0.f, 0.f, 0.f, 0.f};
#pragma unroll
    for (int mt = 0; mt < 2; ++mt)
#pragma unroll
        for (int nt = 0; nt < 8; ++nt) {
            float e0 = __expf(acc[mt][nt][0] - gmx[mt * 2]);
            float e1 = __expf(acc[mt][nt][1] - gmx[mt * 2]);
            float e2 = __expf(acc[mt][nt][2] - gmx[mt * 2 + 1]);
            float e3 = __expf(acc[mt][nt][3] - gmx[mt * 2 + 1]);
            acc[mt][nt][0] = e0; acc[mt][nt][1] = e1;
            acc[mt][nt][2] = e2; acc[mt][nt][3] = e3;
            sme[mt * 2]     += e0 + e1;
            sme[mt * 2 + 1] += e2 + e3;
        }
#pragma unroll
    for (int j = 0; j < 4; ++j) {
        sme[j] += __shfl_xor_sync(0xffffffffu, sme[j], 1);
        sme[j] += __shfl_xor_sync(0xffffffffu, sme[j], 2);
    }
    if (tg == 0) {
#pragma unroll
        for (int j = 0; j < 4; ++j) {
            int rl = wm * 32 + (j >> 1) * 16 + (j & 1) * 8 + gid;
            red[rl * 8 + wn] = sme[j];
        }
    }
    __syncthreads();
    float inv[4];
#pragma unroll
    for (int j = 0; j < 4; ++j) {
        int rl = wm * 32 + (j >> 1) * 16 + (j & 1) * 8 + gid;
        float s = 0.f;
#pragma unroll
        for (int w = 0; w < 8; ++w) s += red[rl * 8 + w];
        inv[j] = 1.f / s;
    }

    // store probs tf32-rounded (so k3 needs no cvt)
#pragma unroll
    for (int mt = 0; mt < 2; ++mt) {
        int r = m0 + wm * 32 + mt * 16 + gid;
        size_t base0 = ((size_t)b * Ldim + r) * Sdim;
        size_t base1 = ((size_t)b * Ldim + r + 8) * Sdim;
#pragma unroll
        for (int nt = 0; nt < 8; ++nt) {
            int col = wn * 64 + nt * 8 + tg * 2;
            *(float2*)(&g_probs[base0 + col]) =
                make_float2(round_tf32(acc[mt][nt][0] * inv[mt * 2]),
                            round_tf32(acc[mt][nt][1] * inv[mt * 2]));
            *(float2*)(&g_probs[base1 + col]) =
                make_float2(round_tf32(acc[mt][nt][2] * inv[mt * 2 + 1]),
                            round_tf32(acc[mt][nt][3] * inv[mt * 2 + 1]));
        }
    }
}

// ---------------- Kernel 3: out = probs @ inputs ----------------
// Per batch: C[8192,768] = P[8192,512(k)] x X[512(k),768(n)]   (NN, pre-rounded)
__global__ __launch_bounds__(256) void k_out(const float* __restrict__ X,
                                             float* __restrict__ O) {
    extern __shared__ __align__(16) float smem[];
    float* As = smem;
    float* Bs = smem + 2 * 128 * 36;
    uint32_t sb  = (uint32_t)__cvta_generic_to_shared(smem);
    const uint32_t sbA = sb;
    const uint32_t sbB = sb + 2u * 128u * 36u * 4u;

    const int tid  = threadIdx.x;
    const int lane = tid & 31, wid = tid >> 5;
    const int wm = wid & 1, wn = wid >> 1;
    const int tg = lane & 3, gid = lane >> 2;
    const int bb = blockIdx.z;
    const int m0 = blockIdx.y * 128, n0 = blockIdx.x * 128;
    const float* gA = g_probs + (size_t)bb * Ldim * Sdim;
    const float* gB = X + (size_t)bb * Sdim * Hdim;

    float acc[4][4][4];
#pragma unroll
    for (int i = 0; i < 4; i++)
#pragma unroll
        for (int j = 0; j < 4; j++)
#pragma unroll
            for (int r = 0; r < 4; r++) acc[i][j][r] = 0.f;

#pragma unroll
    for (int i = 0; i < 4; i++) {
        int idx = tid + i * 256;
        int ra = idx >> 3, ca = (idx & 7) * 4;
        cp16(sbA + (uint32_t)(ra * 36 + ca) * 4u, gA + (size_t)(m0 + ra) * Sdim + ca);
        int rb = idx >> 5, cb = (idx & 31) * 4;
        cp16(sbB + (uint32_t)(rb * 136 + cb) * 4u, gB + (size_t)rb * Hdim + n0 + cb);
    }
    cp_commit();

    const int KT = Sdim / 32;
#pragma unroll 1
    for (int kt = 0; kt < KT; ++kt) {
        int cur = kt & 1;
        if (kt + 1 < KT) {
            int nxt = cur ^ 1;
#pragma unroll
            for (int i = 0; i < 4; i++) {
                int idx = tid + i * 256;
                int ra = idx >> 3, ca = (idx & 7) * 4;
                cp16(sbA + (uint32_t)(nxt * 128 * 36 + ra * 36 + ca) * 4u,
                     gA + (size_t)(m0 + ra) * Sdim + (kt + 1) * 32 + ca);
                int rb = idx >> 5, cb = (idx & 31) * 4;
                cp16(sbB + (uint32_t)(nxt * 32 * 136 + rb * 136 + cb) * 4u,
                     gB + (size_t)((kt + 1) * 32 + rb) * Hdim + n0 + cb);
            }
            cp_commit();
            cp_wait1();
        } else {
            cp_wait0();
        }
        __syncthreads();
        const float* sA = As + cur * 128 * 36;
        const float* sB = Bs + cur * 32 * 136;
#pragma unroll
        for (int kk = 0; kk < 4; ++kk) {
            uint32_t af[4][4], bf[4][2];
#pragma unroll
            for (int mt = 0; mt < 4; ++mt) {
                int r = wm * 64 + mt * 16 + gid;
                af[mt][0] = __float_as_uint(sA[r * 36 + kk * 8 + tg]);
                af[mt][1] = __float_as_uint(sA[(r + 8) * 36 + kk * 8 + tg]);
                af[mt][2] = __float_as_uint(sA[r * 36 + kk * 8 + 4 + tg]);
                af[mt][3] = __float_as_uint(sA[(r + 8) * 36 + kk * 8 + 4 + tg]);
            }
#pragma unroll
            for (int nt = 0; nt < 4; ++nt) {
                int n = wn * 32 + nt * 8 + gid;
                bf[nt][0] = __float_as_uint(sB[(kk * 8 + tg) * 136 + n]);
                bf[nt][1] = __float_as_uint(sB[(kk * 8 + 4 + tg) * 136 + n]);
            }
#pragma unroll
            for (int mt = 0; mt < 4; ++mt)
#pragma unroll
                for (int nt = 0; nt < 4; ++nt)
                    mma_m16n8k8(acc[mt][nt], af[mt], bf[nt]);
        }
        __syncthreads();
    }
#pragma unroll
    for (int mt = 0; mt < 4; ++mt) {
        int r = m0 + wm * 64 + mt * 16 + gid;
        size_t base0 = (size_t)bb * Ldim * Hdim + (size_t)r * Hdim;
        size_t base1 = (size_t)bb * Ldim * Hdim + (size_t)(r + 8) * Hdim;
#pragma unroll
        for (int nt = 0; nt < 4; ++nt) {
            int c = n0 + wn * 32 + nt * 8 + tg * 2;
            *(float2*)(&O[base0 + c]) = make_float2(acc[mt][nt][0], acc[mt][nt][1]);
            *(float2*)(&O[base1 + c]) = make_float2(acc[mt][nt][2], acc[mt][nt][3]);
        }
    }
}

// ---------------- launcher ----------------
extern "C" void kernel_launch(void* const* d_in, const int* in_sizes, int n_in,
                              void* d_out, int out_size) {
    const float* inputs = (const float*)d_in[0];
    const void*  masks  = d_in[1];
    const float* emb    = (const float*)d_in[2];
    const float* wkey   = (const float*)d_in[3];
    float* out = (float*)d_out;
    (void)in_sizes; (void)n_in; (void)out_size;

    cudaFuncSetAttribute(k_keyproj, cudaFuncAttributeMaxDynamicSharedMemorySize, 73728);
    cudaFuncSetAttribute(k_scores,  cudaFuncAttributeMaxDynamicSharedMemorySize, K2_SMEM_BYTES);
    cudaFuncSetAttribute(k_out,     cudaFuncAttributeMaxDynamicSharedMemorySize, 71680);

    float* d_xr; cudaGetSymbolAddress((void**)&d_xr, g_xr);
    float* d_er; cudaGetSymbolAddress((void**)&d_er, g_er);
    float* d_wr; cudaGetSymbolAddress((void**)&d_wr, g_wr);

    k_detect<<<1, 256>>>((const int*)masks);
    k_round<<<512, 256>>>((const float4*)inputs, (float4*)d_xr, Bdim * Sdim * Hdim / 4);
    k_round<<<512, 256>>>((const float4*)emb,    (float4*)d_er, Ldim * Hdim / 4);
    k_round<<<512, 256>>>((const float4*)wkey,   (float4*)d_wr, Hdim * Hdim / 4);
    k_keyproj<<<dim3(6, 32, 1), 256, 73728>>>(d_xr, d_wr);
    k_scores<<<dim3(Ldim / 64, Bdim, 1), 512, K2_SMEM_BYTES>>>(d_er, masks);
    k_out<<<dim3(6, Ldim / 128, Bdim), 256, 71680>>>(d_xr, out);
}

// round 5
// speedup vs baseline: 1.7285x; 1.4678x over previous
#include <cuda_runtime.h>
#include <cuda_fp16.h>
#include <cstdint>

#define Bdim 8
#define Sdim 512
#define Hdim 768
#define Ldim 8192

// scratch (static device globals: allocation-free)
__device__ __half g_xh[Bdim * Sdim * Hdim];                 // inputs as fp16
__device__ __half g_xth[Bdim * Hdim * Sdim];                // inputs^T [B,H,S] fp16
__device__ __half g_eh[Ldim * Hdim];                        // label_embedding fp16
__device__ __half g_wh[Hdim * Hdim];                        // W_key fp16
__device__ __half g_akh[Bdim * Sdim * Hdim];                // attn_key fp16
__device__ __half g_ph[(size_t)Bdim * Ldim * Sdim];         // probs fp16 (67 MB)
__device__ int    g_mask_is_i32;

// ---------------- PTX helpers ----------------
__device__ __forceinline__ void mma_f16(float* c, const uint32_t* a, const uint32_t* b) {
    asm volatile(
        "mma.sync.aligned.m16n8k16.row.col.f32.f16.f16.f32 "
        "{%0,%1,%2,%3}, {%4,%5,%6,%7}, {%8,%9}, {%0,%1,%2,%3};\n"
        : "+f"(c[0]), "+f"(c[1]), "+f"(c[2]), "+f"(c[3])
        : "r"(a[0]), "r"(a[1]), "r"(a[2]), "r"(a[3]), "r"(b[0]), "r"(b[1]));
}

__device__ __forceinline__ void cp16(uint32_t s, const void* g) {
    asm volatile("cp.async.cg.shared.global [%0], [%1], 16;\n" :: "r"(s), "l"(g));
}
__device__ __forceinline__ void cp_commit() { asm volatile("cp.async.commit_group;\n"); }
__device__ __forceinline__ void cp_wait1()  { asm volatile("cp.async.wait_group 1;\n"); }
__device__ __forceinline__ void cp_wait0()  { asm volatile("cp.async.wait_group 0;\n"); }

__device__ __forceinline__ uint32_t lds32(const __half* p) {
    return *(const uint32_t*)p;
}

// ---------------- prep: fp32 -> fp16 ----------------
__global__ void k_cvt(const float4* __restrict__ src, uint4* __restrict__ dst, int n8) {
    int i = blockIdx.x * blockDim.x + threadIdx.x;
    int stride = gridDim.x * blockDim.x;
    for (; i < n8; i += stride) {
        float4 a = src[2 * i], b = src[2 * i + 1];
        __half2 h0 = __floats2half2_rn(a.x, a.y);
        __half2 h1 = __floats2half2_rn(a.z, a.w);
        __half2 h2 = __floats2half2_rn(b.x, b.y);
        __half2 h3 = __floats2half2_rn(b.z, b.w);
        uint4 o;
        o.x = *(uint32_t*)&h0; o.y = *(uint32_t*)&h1;
        o.z = *(uint32_t*)&h2; o.w = *(uint32_t*)&h3;
        dst[i] = o;
    }
}

// transpose+convert: XT[b][h][s] = half(X[b][s][h])
__global__ void k_trh(const float* __restrict__ X, __half* __restrict__ XT) {
    __shared__ float t[32][33];
    int b = blockIdx.z;
    int s0 = blockIdx.y * 32, h0 = blockIdx.x * 32;
    int x = threadIdx.x, y = threadIdx.y;  // 32 x 8
    const float* src = X + ((size_t)b * Sdim + s0) * Hdim + h0;
#pragma unroll
    for (int i = 0; i < 32; i += 8)
        t[y + i][x] = src[(size_t)(y + i) * Hdim + x];
    __syncthreads();
    __half* dst = XT + ((size_t)b * Hdim + h0) * Sdim + s0;
#pragma unroll
    for (int i = 0; i < 32; i += 8)
        dst[(size_t)(y + i) * Sdim + x] = __float2half_rn(t[x][y + i]);
}

// ---------------- mask dtype detection ----------------
__global__ void k_detect(const int* __restrict__ m) {
    __shared__ int bad;
    if (threadIdx.x == 0) bad = 0;
    __syncthreads();
    int local = 0;
#pragma unroll
    for (int i = 0; i < 4; i++) {
        unsigned v = (unsigned)m[threadIdx.x + i * 256];
        if (v > 1u) local = 1;
    }
    if (local) atomicOr(&bad, 1);
    __syncthreads();
    if (threadIdx.x == 0) g_mask_is_i32 = bad ? 0 : 1;
}

// Row stride in halves for all operand tiles (conflict-free: r*20 mod 32 distinct)
#define RS 40

// ---------------- Kernel 1: attn_key = inputs @ W_key^T ----------------
// C[4096,768] = A[4096,768(k)] x W[768(n),768(k)]  NT, fp16 operands
// BM=128 BN=128 BK=32, 256 threads (warps 2x4, WM=64 WN=32)
__global__ __launch_bounds__(256) void k_keyproj(const __half* __restrict__ A,
                                                 const __half* __restrict__ W) {
    extern __shared__ __align__(16) float smem[];
    __half* As = (__half*)smem;                    // [2][128*RS]
    __half* Bs = (__half*)smem + 2 * 128 * RS;     // [2][128*RS]
    uint32_t sb  = (uint32_t)__cvta_generic_to_shared(smem);
    const uint32_t sbA = sb;
    const uint32_t sbB = sb + 2u * 128u * RS * 2u;

    const int tid  = threadIdx.x;
    const int lane = tid & 31, wid = tid >> 5;
    const int wm = wid & 1, wn = wid >> 1;
    const int tg = lane & 3, gid = lane >> 2;
    const int m0 = blockIdx.y * 128, n0 = blockIdx.x * 128;

    float acc[4][4][4];
#pragma unroll
    for (int i = 0; i < 4; i++)
#pragma unroll
        for (int j = 0; j < 4; j++)
#pragma unroll
            for (int r = 0; r < 4; r++) acc[i][j][r] = 0.f;

    // stage 0: 128 rows x 32 halves = 128*4 cp16 per operand
#pragma unroll
    for (int i = 0; i < 2; i++) {
        int idx = tid + i * 256;
        int r = idx >> 2, c = (idx & 3) * 8;
        cp16(sbA + (uint32_t)(r * RS + c) * 2u, A + (size_t)(m0 + r) * Hdim + c);
        cp16(sbB + (uint32_t)(r * RS + c) * 2u, W + (size_t)(n0 + r) * Hdim + c);
    }
    cp_commit();

    const int KT = Hdim / 32;  // 24
#pragma unroll 1
    for (int kt = 0; kt < KT; ++kt) {
        int cur = kt & 1;
        if (kt + 1 < KT) {
            int nxt = cur ^ 1;
#pragma unroll
            for (int i = 0; i < 2; i++) {
                int idx = tid + i * 256;
                int r = idx >> 2, c = (idx & 3) * 8;
                cp16(sbA + (uint32_t)(nxt * 128 * RS + r * RS + c) * 2u,
                     A + (size_t)(m0 + r) * Hdim + (kt + 1) * 32 + c);
                cp16(sbB + (uint32_t)(nxt * 128 * RS + r * RS + c) * 2u,
                     W + (size_t)(n0 + r) * Hdim + (kt + 1) * 32 + c);
            }
            cp_commit();
            cp_wait1();
        } else {
            cp_wait0();
        }
        __syncthreads();
        const __half* sA = As + cur * 128 * RS;
        const __half* sB = Bs + cur * 128 * RS;
#pragma unroll
        for (int kk = 0; kk < 2; ++kk) {
            uint32_t af[4][4], bf[4][2];
#pragma unroll
            for (int mt = 0; mt < 4; ++mt) {
                int r = wm * 64 + mt * 16 + gid;
                af[mt][0] = lds32(&sA[r * RS + kk * 16 + tg * 2]);
                af[mt][1] = lds32(&sA[(r + 8) * RS + kk * 16 + tg * 2]);
                af[mt][2] = lds32(&sA[r * RS + kk * 16 + 8 + tg * 2]);
                af[mt][3] = lds32(&sA[(r + 8) * RS + kk * 16 + 8 + tg * 2]);
            }
#pragma unroll
            for (int nt = 0; nt < 4; ++nt) {
                int n = wn * 32 + nt * 8 + gid;
                bf[nt][0] = lds32(&sB[n * RS + kk * 16 + tg * 2]);
                bf[nt][1] = lds32(&sB[n * RS + kk * 16 + 8 + tg * 2]);
            }
#pragma unroll
            for (int mt = 0; mt < 4; ++mt)
#pragma unroll
                for (int nt = 0; nt < 4; ++nt)
                    mma_f16(acc[mt][nt], af[mt], bf[nt]);
        }
        __syncthreads();
    }
    // epilogue: store fp16 attn_key
#pragma unroll
    for (int mt = 0; mt < 4; ++mt) {
        int r = m0 + wm * 64 + mt * 16 + gid;
#pragma unroll
        for (int nt = 0; nt < 4; ++nt) {
            int c = n0 + wn * 32 + nt * 8 + tg * 2;
            *(__half2*)(&g_akh[(size_t)r * Hdim + c]) =
                __floats2half2_rn(acc[mt][nt][0], acc[mt][nt][1]);
            *(__half2*)(&g_akh[(size_t)(r + 8) * Hdim + c]) =
                __floats2half2_rn(acc[mt][nt][2], acc[mt][nt][3]);
        }
    }
}

// ---------------- Kernel 2: probs = softmax(mask(E @ attn_key[b]^T)) --------
// BM=64 BN=512 BK=32, 512 threads (warps 2x8, WM=32 WN=64)
#define K2_OFF_B   (2 * 64 * RS)                 // halves offset of B region
#define K2_OFF_RED (K2_OFF_B + 2 * 512 * RS)     // halves offset of red (as bytes*2)
#define K2_SMEM_BYTES ((K2_OFF_RED) * 2 + 64 * 8 * 4 + 512 + 256)

__global__ __launch_bounds__(512) void k_scores(const __half* __restrict__ E,
                                                const void* __restrict__ masks) {
    extern __shared__ __align__(16) float smem[];
    __half* As = (__half*)smem;
    __half* Bs = (__half*)smem + K2_OFF_B;
    float* red = (float*)((char*)smem + (size_t)K2_OFF_RED * 2);
    unsigned char* msk = (unsigned char*)red + 64 * 8 * 4;
    uint32_t sb  = (uint32_t)__cvta_generic_to_shared(smem);
    const uint32_t sbA = sb;
    const uint32_t sbB = sb + (uint32_t)K2_OFF_B * 2u;

    const int tid  = threadIdx.x;
    const int lane = tid & 31, wid = tid >> 5;
    const int wm = wid & 1, wn = wid >> 1;  // 2 x 8
    const int tg = lane & 3, gid = lane >> 2;
    const int b  = blockIdx.y;
    const int m0 = blockIdx.x * 64;
    const __half* Bt = g_akh + (size_t)b * Sdim * Hdim;

    {
        int is32 = g_mask_is_i32;
        unsigned v = is32 ? (unsigned)((const int*)masks)[b * Sdim + tid]
                          : (unsigned)((const unsigned char*)masks)[b * Sdim + tid];
        msk[tid] = v ? 1 : 0;
    }

    float acc[2][8][4];
#pragma unroll
    for (int i = 0; i < 2; i++)
#pragma unroll
        for (int j = 0; j < 8; j++)
#pragma unroll
            for (int r = 0; r < 4; r++) acc[i][j][r] = 0.f;

    // stage 0: A 64x32 halves = 256 cp16 ; B 512x32 = 2048 cp16
    if (tid < 256) {
        int r = tid >> 2, c = (tid & 3) * 8;
        cp16(sbA + (uint32_t)(r * RS + c) * 2u, E + (size_t)(m0 + r) * Hdim + c);
    }
#pragma unroll
    for (int i = 0; i < 4; i++) {
        int idx = tid + i * 512;
        int r = idx >> 2, c = (idx & 3) * 8;
        cp16(sbB + (uint32_t)(r * RS + c) * 2u, Bt + (size_t)r * Hdim + c);
    }
    cp_commit();

    const int KT = Hdim / 32;  // 24
#pragma unroll 1
    for (int kt = 0; kt < KT; ++kt) {
        int cur = kt & 1;
        if (kt + 1 < KT) {
            int nxt = cur ^ 1;
            if (tid < 256) {
                int r = tid >> 2, c = (tid & 3) * 8;
                cp16(sbA + (uint32_t)(nxt * 64 * RS + r * RS + c) * 2u,
                     E + (size_t)(m0 + r) * Hdim + (kt + 1) * 32 + c);
            }
#pragma unroll
            for (int i = 0; i < 4; i++) {
                int idx = tid + i * 512;
                int r = idx >> 2, c = (idx & 3) * 8;
                cp16(sbB + (uint32_t)(nxt * 512 * RS + r * RS + c) * 2u,
                     Bt + (size_t)r * Hdim + (kt + 1) * 32 + c);
            }
            cp_commit();
            cp_wait1();
        } else {
            cp_wait0();
        }
        __syncthreads();
        const __half* sA = As + cur * 64 * RS;
        const __half* sB = Bs + cur * 512 * RS;
#pragma unroll
        for (int kk = 0; kk < 2; ++kk) {
            uint32_t af[2][4], bf[8][2];
#pragma unroll
            for (int mt = 0; mt < 2; ++mt) {
                int r = wm * 32 + mt * 16 + gid;
                af[mt][0] = lds32(&sA[r * RS + kk * 16 + tg * 2]);
                af[mt][1] = lds32(&sA[(r + 8) * RS + kk * 16 + tg * 2]);
                af[mt][2] = lds32(&sA[r * RS + kk * 16 + 8 + tg * 2]);
                af[mt][3] = lds32(&sA[(r + 8) * RS + kk * 16 + 8 + tg * 2]);
            }
#pragma unroll
            for (int nt = 0; nt < 8; ++nt) {
                int n = wn * 64 + nt * 8 + gid;
                bf[nt][0] = lds32(&sB[n * RS + kk * 16 + tg * 2]);
                bf[nt][1] = lds32(&sB[n * RS + kk * 16 + 8 + tg * 2]);
            }
#pragma unroll
            for (int mt = 0; mt < 2; ++mt)
#pragma unroll
                for (int nt = 0; nt < 8; ++nt)
                    mma_f16(acc[mt][nt], af[mt], bf[nt]);
        }
        __syncthreads();
    }

    // ---- masked softmax epilogue (fp32) ----
    float mx[4] = {-1e30f, -1e30f, -1e30f, -1e30f};
#pragma unroll
    for (int mt = 0; mt < 2; ++mt)
#pragma unroll
        for (int nt = 0; nt < 8; ++nt) {
            int col = wn * 64 + nt * 8 + tg * 2;
            bool m0ok = msk[col] != 0, m1ok = msk[col + 1] != 0;
            if (!m0ok) { acc[mt][nt][0] = -1e30f; acc[mt][nt][2] = -1e30f; }
            if (!m1ok) { acc[mt][nt][1] = -1e30f; acc[mt][nt][3] = -1e30f; }
            mx[mt * 2]     = fmaxf(mx[mt * 2],     fmaxf(acc[mt][nt][0], acc[mt][nt][1]));
            mx[mt * 2 + 1] = fmaxf(mx[mt * 2 + 1], fmaxf(acc[mt][nt][2], acc[mt][nt][3]));
        }
#pragma unroll
    for (int j = 0; j < 4; ++j) {
        mx[j] = fmaxf(mx[j], __shfl_xor_sync(0xffffffffu, mx[j], 1));
        mx[j] = fmaxf(mx[j], __shfl_xor_sync(0xffffffffu, mx[j], 2));
    }
    if (tg == 0) {
#pragma unroll
        for (int j = 0; j < 4; ++j) {
            int rl = wm * 32 + (j >> 1) * 16 + (j & 1) * 8 + gid;
            red[rl * 8 + wn] = mx[j];
        }
    }
    __syncthreads();
    float gmx[4];
#pragma unroll
    for (int j = 0; j < 4; ++j) {
        int rl = wm * 32 + (j >> 1) * 16 + (j & 1) * 8 + gid;
        float m = -1e30f;
#pragma unroll
        for (int w = 0; w < 8; ++w) m = fmaxf(m, red[rl * 8 + w]);
        gmx[j] = m;
    }
    __syncthreads();

    float sme[4] = {0.f, 0.f, 0.f, 0.f};
#pragma unroll
    for (int mt = 0; mt < 2; ++mt)
#pragma unroll
        for (int nt = 0; nt < 8; ++nt) {
            float e0 = __expf(acc[mt][nt][0] - gmx[mt * 2]);
            float e1 = __expf(acc[mt][nt][1] - gmx[mt * 2]);
            float e2 = __expf(acc[mt][nt][2] - gmx[mt * 2 + 1]);
            float e3 = __expf(acc[mt][nt][3] - gmx[mt * 2 + 1]);
            acc[mt][nt][0] = e0; acc[mt][nt][1] = e1;
            acc[mt][nt][2] = e2; acc[mt][nt][3] = e3;
            sme[mt * 2]     += e0 + e1;
            sme[mt * 2 + 1] += e2 + e3;
        }
#pragma unroll
    for (int j = 0; j < 4; ++j) {
        sme[j] += __shfl_xor_sync(0xffffffffu, sme[j], 1);
        sme[j] += __shfl_xor_sync(0xffffffffu, sme[j], 2);
    }
    if (tg == 0) {
#pragma unroll
        for (int j = 0; j < 4; ++j) {
            int rl = wm * 32 + (j >> 1) * 16 + (j & 1) * 8 + gid;
            red[rl * 8 + wn] = sme[j];
        }
    }
    __syncthreads();
    float inv[4];
#pragma unroll
    for (int j = 0; j < 4; ++j) {
        int rl = wm * 32 + (j >> 1) * 16 + (j & 1) * 8 + gid;
        float s = 0.f;
#pragma unroll
        for (int w = 0; w < 8; ++w) s += red[rl * 8 + w];
        inv[j] = 1.f / s;
    }

    // store probs as fp16
#pragma unroll
    for (int mt = 0; mt < 2; ++mt) {
        int r = m0 + wm * 32 + mt * 16 + gid;
        size_t base0 = ((size_t)b * Ldim + r) * Sdim;
        size_t base1 = ((size_t)b * Ldim + r + 8) * Sdim;
#pragma unroll
        for (int nt = 0; nt < 8; ++nt) {
            int col = wn * 64 + nt * 8 + tg * 2;
            *(__half2*)(&g_ph[base0 + col]) =
                __floats2half2_rn(acc[mt][nt][0] * inv[mt * 2], acc[mt][nt][1] * inv[mt * 2]);
            *(__half2*)(&g_ph[base1 + col]) =
                __floats2half2_rn(acc[mt][nt][2] * inv[mt * 2 + 1], acc[mt][nt][3] * inv[mt * 2 + 1]);
        }
    }
}

// ---------------- Kernel 3: out = probs @ inputs ----------------
// Per batch: C[8192,768] = P[8192,512(k)] x XT[768(n),512(k)]  NT fp16
// BM=128 BN=128 BK=32, 256 threads (warps 2x4)
__global__ __launch_bounds__(256) void k_out(const __half* __restrict__ XT,
                                             float* __restrict__ O) {
    extern __shared__ __align__(16) float smem[];
    __half* As = (__half*)smem;
    __half* Bs = (__half*)smem + 2 * 128 * RS;
    uint32_t sb  = (uint32_t)__cvta_generic_to_shared(smem);
    const uint32_t sbA = sb;
    const uint32_t sbB = sb + 2u * 128u * RS * 2u;

    const int tid  = threadIdx.x;
    const int lane = tid & 31, wid = tid >> 5;
    const int wm = wid & 1, wn = wid >> 1;
    const int tg = lane & 3, gid = lane >> 2;
    const int bb = blockIdx.z;
    const int m0 = blockIdx.y * 128, n0 = blockIdx.x * 128;
    const __half* gA = g_ph + ((size_t)bb * Ldim + m0) * Sdim;
    const __half* gB = XT + ((size_t)bb * Hdim + n0) * Sdim;

    float acc[4][4][4];
#pragma unroll
    for (int i = 0; i < 4; i++)
#pragma unroll
        for (int j = 0; j < 4; j++)
#pragma unroll
            for (int r = 0; r < 4; r++) acc[i][j][r] = 0.f;

#pragma unroll
    for (int i = 0; i < 2; i++) {
        int idx = tid + i * 256;
        int r = idx >> 2, c = (idx & 3) * 8;
        cp16(sbA + (uint32_t)(r * RS + c) * 2u, gA + (size_t)r * Sdim + c);
        cp16(sbB + (uint32_t)(r * RS + c) * 2u, gB + (size_t)r * Sdim + c);
    }
    cp_commit();

    const int KT = Sdim / 32;  // 16
#pragma unroll 1
    for (int kt = 0; kt < KT; ++kt) {
        int cur = kt & 1;
        if (kt + 1 < KT) {
            int nxt = cur ^ 1;
#pragma unroll
            for (int i = 0; i < 2; i++) {
                int idx = tid + i * 256;
                int r = idx >> 2, c = (idx & 3) * 8;
                cp16(sbA + (uint32_t)(nxt * 128 * RS + r * RS + c) * 2u,
                     gA + (size_t)r * Sdim + (kt + 1) * 32 + c);
                cp16(sbB + (uint32_t)(nxt * 128 * RS + r * RS + c) * 2u,
                     gB + (size_t)r * Sdim + (kt + 1) * 32 + c);
            }
            cp_commit();
            cp_wait1();
        } else {
            cp_wait0();
        }
        __syncthreads();
        const __half* sA = As + cur * 128 * RS;
        const __half* sB = Bs + cur * 128 * RS;
#pragma unroll
        for (int kk = 0; kk < 2; ++kk) {
            uint32_t af[4][4], bf[4][2];
#pragma unroll
            for (int mt = 0; mt < 4; ++mt) {
                int r = wm * 64 + mt * 16 + gid;
                af[mt][0] = lds32(&sA[r * RS + kk * 16 + tg * 2]);
                af[mt][1] = lds32(&sA[(r + 8) * RS + kk * 16 + tg * 2]);
                af[mt][2] = lds32(&sA[r * RS + kk * 16 + 8 + tg * 2]);
                af[mt][3] = lds32(&sA[(r + 8) * RS + kk * 16 + 8 + tg * 2]);
            }
#pragma unroll
            for (int nt = 0; nt < 4; ++nt) {
                int n = wn * 32 + nt * 8 + gid;
                bf[nt][0] = lds32(&sB[n * RS + kk * 16 + tg * 2]);
                bf[nt][1] = lds32(&sB[n * RS + kk * 16 + 8 + tg * 2]);
            }
#pragma unroll
            for (int mt = 0; mt < 4; ++mt)
#pragma unroll
                for (int nt = 0; nt < 4; ++nt)
                    mma_f16(acc[mt][nt], af[mt], bf[nt]);
        }
        __syncthreads();
    }
#pragma unroll
    for (int mt = 0; mt < 4; ++mt) {
        int r = m0 + wm * 64 + mt * 16 + gid;
        size_t base0 = (size_t)bb * Ldim * Hdim + (size_t)r * Hdim;
        size_t base1 = (size_t)bb * Ldim * Hdim + (size_t)(r + 8) * Hdim;
#pragma unroll
        for (int nt = 0; nt < 4; ++nt) {
            int c = n0 + wn * 32 + nt * 8 + tg * 2;
            *(float2*)(&O[base0 + c]) = make_float2(acc[mt][nt][0], acc[mt][nt][1]);
            *(float2*)(&O[base1 + c]) = make_float2(acc[mt][nt][2], acc[mt][nt][3]);
        }
    }
}

// ---------------- launcher ----------------
#define K1_SMEM_BYTES (4 * 128 * RS * 2)
#define K3_SMEM_BYTES (4 * 128 * RS * 2)

extern "C" void kernel_launch(void* const* d_in, const int* in_sizes, int n_in,
                              void* d_out, int out_size) {
    const float* inputs = (const float*)d_in[0];
    const void*  masks  = d_in[1];
    const float* emb    = (const float*)d_in[2];
    const float* wkey   = (const float*)d_in[3];
    float* out = (float*)d_out;
    (void)in_sizes; (void)n_in; (void)out_size;

    cudaFuncSetAttribute(k_keyproj, cudaFuncAttributeMaxDynamicSharedMemorySize, K1_SMEM_BYTES);
    cudaFuncSetAttribute(k_scores,  cudaFuncAttributeMaxDynamicSharedMemorySize, K2_SMEM_BYTES);
    cudaFuncSetAttribute(k_out,     cudaFuncAttributeMaxDynamicSharedMemorySize, K3_SMEM_BYTES);

    __half* d_xh;  cudaGetSymbolAddress((void**)&d_xh,  g_xh);
    __half* d_xth; cudaGetSymbolAddress((void**)&d_xth, g_xth);
    __half* d_eh;  cudaGetSymbolAddress((void**)&d_eh,  g_eh);
    __half* d_wh;  cudaGetSymbolAddress((void**)&d_wh,  g_wh);

    k_detect<<<1, 256>>>((const int*)masks);
    k_cvt<<<512, 256>>>((const float4*)inputs, (uint4*)d_xh, Bdim * Sdim * Hdim / 8);
    k_cvt<<<512, 256>>>((const float4*)emb,    (uint4*)d_eh, Ldim * Hdim / 8);
    k_cvt<<<256, 256>>>((const float4*)wkey,   (uint4*)d_wh, Hdim * Hdim / 8);
    k_trh<<<dim3(Hdim / 32, Sdim / 32, Bdim), dim3(32, 8)>>>(inputs, d_xth);
    k_keyproj<<<dim3(6, 32, 1), 256, K1_SMEM_BYTES>>>(d_xh, d_wh);
    k_scores<<<dim3(Ldim / 64, Bdim, 1), 512, K2_SMEM_BYTES>>>(d_eh, masks);
    k_out<<<dim3(6, Ldim / 128, Bdim), 256, K3_SMEM_BYTES>>>(d_xth, out);
}

// round 6
// speedup vs baseline: 1.8123x; 1.0485x over previous
#include <cuda_runtime.h>
#include <cuda_fp16.h>
#include <cstdint>

#define Bdim 8
#define Sdim 512
#define Hdim 768
#define Ldim 8192

// scratch (static device globals: allocation-free)
__device__ __half g_xh[Bdim * Sdim * Hdim];                 // inputs as fp16
__device__ __half g_xth[Bdim * Hdim * Sdim];                // inputs^T [B,H,S] fp16
__device__ __half g_eh[Ldim * Hdim];                        // label_embedding fp16
__device__ __half g_wh[Hdim * Hdim];                        // W_key fp16
__device__ __half g_akh[Bdim * Sdim * Hdim];                // attn_key fp16
__device__ __half g_ph[(size_t)Bdim * Ldim * Sdim];         // probs fp16 (67 MB)
__device__ int    g_mask_is_i32;

// ---------------- PTX helpers ----------------
__device__ __forceinline__ void mma_f16(float* c, const uint32_t* a, const uint32_t* b) {
    asm volatile(
        "mma.sync.aligned.m16n8k16.row.col.f32.f16.f16.f32 "
        "{%0,%1,%2,%3}, {%4,%5,%6,%7}, {%8,%9}, {%0,%1,%2,%3};\n"
        : "+f"(c[0]), "+f"(c[1]), "+f"(c[2]), "+f"(c[3])
        : "r"(a[0]), "r"(a[1]), "r"(a[2]), "r"(a[3]), "r"(b[0]), "r"(b[1]));
}

__device__ __forceinline__ void ldsm_x4(uint32_t& r0, uint32_t& r1, uint32_t& r2,
                                        uint32_t& r3, uint32_t addr) {
    asm volatile("ldmatrix.sync.aligned.m8n8.x4.shared.b16 {%0,%1,%2,%3}, [%4];"
                 : "=r"(r0), "=r"(r1), "=r"(r2), "=r"(r3) : "r"(addr));
}

__device__ __forceinline__ void cp16(uint32_t s, const void* g) {
    asm volatile("cp.async.cg.shared.global [%0], [%1], 16;\n" :: "r"(s), "l"(g));
}
__device__ __forceinline__ void cp_commit() { asm volatile("cp.async.commit_group;\n"); }
__device__ __forceinline__ void cp_wait1()  { asm volatile("cp.async.wait_group 1;\n"); }
__device__ __forceinline__ void cp_wait0()  { asm volatile("cp.async.wait_group 0;\n"); }

// ---------------- prep: fp32 -> fp16 ----------------
__global__ void k_cvt(const float4* __restrict__ src, uint4* __restrict__ dst, int n8) {
    int i = blockIdx.x * blockDim.x + threadIdx.x;
    int stride = gridDim.x * blockDim.x;
    for (; i < n8; i += stride) {
        float4 a = src[2 * i], b = src[2 * i + 1];
        __half2 h0 = __floats2half2_rn(a.x, a.y);
        __half2 h1 = __floats2half2_rn(a.z, a.w);
        __half2 h2 = __floats2half2_rn(b.x, b.y);
        __half2 h3 = __floats2half2_rn(b.z, b.w);
        uint4 o;
        o.x = *(uint32_t*)&h0; o.y = *(uint32_t*)&h1;
        o.z = *(uint32_t*)&h2; o.w = *(uint32_t*)&h3;
        dst[i] = o;
    }
}

// transpose+convert: XT[b][h][s] = half(X[b][s][h])
__global__ void k_trh(const float* __restrict__ X, __half* __restrict__ XT) {
    __shared__ float t[32][33];
    int b = blockIdx.z;
    int s0 = blockIdx.y * 32, h0 = blockIdx.x * 32;
    int x = threadIdx.x, y = threadIdx.y;  // 32 x 8
    const float* src = X + ((size_t)b * Sdim + s0) * Hdim + h0;
#pragma unroll
    for (int i = 0; i < 32; i += 8)
        t[y + i][x] = src[(size_t)(y + i) * Hdim + x];
    __syncthreads();
    __half* dst = XT + ((size_t)b * Hdim + h0) * Sdim + s0;
#pragma unroll
    for (int i = 0; i < 32; i += 8)
        dst[(size_t)(y + i) * Sdim + x] = __float2half_rn(t[x][y + i]);
}

// ---------------- mask dtype detection ----------------
__global__ void k_detect(const int* __restrict__ m) {
    __shared__ int bad;
    if (threadIdx.x == 0) bad = 0;
    __syncthreads();
    int local = 0;
#pragma unroll
    for (int i = 0; i < 4; i++) {
        unsigned v = (unsigned)m[threadIdx.x + i * 256];
        if (v > 1u) local = 1;
    }
    if (local) atomicOr(&bad, 1);
    __syncthreads();
    if (threadIdx.x == 0) g_mask_is_i32 = bad ? 0 : 1;
}

// Row stride in halves (80B): LDSM rows hit distinct 16B segs mod 128 -> conflict-free
#define RS 40

// ---------------- Kernel 1: attn_key = inputs @ W_key^T ----------------
// BM=128 BN=128 BK=32, 256 threads (warps 2x4, WM=64 WN=32)
__global__ __launch_bounds__(256) void k_keyproj(const __half* __restrict__ A,
                                                 const __half* __restrict__ W) {
    extern __shared__ __align__(16) float smem[];
    uint32_t sb  = (uint32_t)__cvta_generic_to_shared(smem);
    const uint32_t sbA = sb;
    const uint32_t sbB = sb + 2u * 128u * RS * 2u;

    const int tid  = threadIdx.x;
    const int lane = tid & 31, wid = tid >> 5;
    const int wm = wid & 1, wn = wid >> 1;
    const int tg = lane & 3, gid = lane >> 2;
    const int m0 = blockIdx.y * 128, n0 = blockIdx.x * 128;

    // LDSM per-lane offsets (in halves)
    const int a_row = lane & 15, a_kh = (lane >> 4) << 3;
    const int b_row = ((lane >> 4) << 3) + (lane & 7), b_kh = ((lane >> 3) & 1) << 3;

    float acc[4][4][4];
#pragma unroll
    for (int i = 0; i < 4; i++)
#pragma unroll
        for (int j = 0; j < 4; j++)
#pragma unroll
            for (int r = 0; r < 4; r++) acc[i][j][r] = 0.f;

#pragma unroll
    for (int i = 0; i < 2; i++) {
        int idx = tid + i * 256;
        int r = idx >> 2, c = (idx & 3) * 8;
        cp16(sbA + (uint32_t)(r * RS + c) * 2u, A + (size_t)(m0 + r) * Hdim + c);
        cp16(sbB + (uint32_t)(r * RS + c) * 2u, W + (size_t)(n0 + r) * Hdim + c);
    }
    cp_commit();

    const int KT = Hdim / 32;  // 24
#pragma unroll 1
    for (int kt = 0; kt < KT; ++kt) {
        int cur = kt & 1;
        if (kt + 1 < KT) {
            int nxt = cur ^ 1;
#pragma unroll
            for (int i = 0; i < 2; i++) {
                int idx = tid + i * 256;
                int r = idx >> 2, c = (idx & 3) * 8;
                cp16(sbA + (uint32_t)(nxt * 128 * RS + r * RS + c) * 2u,
                     A + (size_t)(m0 + r) * Hdim + (kt + 1) * 32 + c);
                cp16(sbB + (uint32_t)(nxt * 128 * RS + r * RS + c) * 2u,
                     W + (size_t)(n0 + r) * Hdim + (kt + 1) * 32 + c);
            }
            cp_commit();
            cp_wait1();
        } else {
            cp_wait0();
        }
        __syncthreads();
        const uint32_t aBase = sbA + (uint32_t)(cur * 128 * RS) * 2u;
        const uint32_t bBase = sbB + (uint32_t)(cur * 128 * RS) * 2u;
#pragma unroll
        for (int kk = 0; kk < 2; ++kk) {
            uint32_t af[4][4], bf[4][2];
#pragma unroll
            for (int mt = 0; mt < 4; ++mt)
                ldsm_x4(af[mt][0], af[mt][1], af[mt][2], af[mt][3],
                        aBase + (uint32_t)(((wm * 64 + mt * 16 + a_row) * RS + kk * 16 + a_kh) * 2));
#pragma unroll
            for (int p = 0; p < 2; ++p)
                ldsm_x4(bf[2 * p][0], bf[2 * p][1], bf[2 * p + 1][0], bf[2 * p + 1][1],
                        bBase + (uint32_t)(((wn * 32 + p * 16 + b_row) * RS + kk * 16 + b_kh) * 2));
#pragma unroll
            for (int mt = 0; mt < 4; ++mt)
#pragma unroll
                for (int nt = 0; nt < 4; ++nt)
                    mma_f16(acc[mt][nt], af[mt], bf[nt]);
        }
        __syncthreads();
    }
#pragma unroll
    for (int mt = 0; mt < 4; ++mt) {
        int r = m0 + wm * 64 + mt * 16 + gid;
#pragma unroll
        for (int nt = 0; nt < 4; ++nt) {
            int c = n0 + wn * 32 + nt * 8 + tg * 2;
            *(__half2*)(&g_akh[(size_t)r * Hdim + c]) =
                __floats2half2_rn(acc[mt][nt][0], acc[mt][nt][1]);
            *(__half2*)(&g_akh[(size_t)(r + 8) * Hdim + c]) =
                __floats2half2_rn(acc[mt][nt][2], acc[mt][nt][3]);
        }
    }
}

// ---------------- Kernel 2: probs = softmax(mask(E @ attn_key[b]^T)) --------
// BM=64 BN=512 BK=32, 512 threads (warps 2x8, WM=32 WN=64)
#define K2_OFF_B   (2 * 64 * RS)
#define K2_OFF_RED (K2_OFF_B + 2 * 512 * RS)
#define K2_SMEM_BYTES ((K2_OFF_RED) * 2 + 64 * 8 * 4 + 512 + 256)

__global__ __launch_bounds__(512) void k_scores(const __half* __restrict__ E,
                                                const void* __restrict__ masks) {
    extern __shared__ __align__(16) float smem[];
    float* red = (float*)((char*)smem + (size_t)K2_OFF_RED * 2);
    unsigned char* msk = (unsigned char*)red + 64 * 8 * 4;
    uint32_t sb  = (uint32_t)__cvta_generic_to_shared(smem);
    const uint32_t sbA = sb;
    const uint32_t sbB = sb + (uint32_t)K2_OFF_B * 2u;

    const int tid  = threadIdx.x;
    const int lane = tid & 31, wid = tid >> 5;
    const int wm = wid & 1, wn = wid >> 1;  // 2 x 8
    const int tg = lane & 3, gid = lane >> 2;
    const int b  = blockIdx.y;
    const int m0 = blockIdx.x * 64;
    const __half* Bt = g_akh + (size_t)b * Sdim * Hdim;

    const int a_row = lane & 15, a_kh = (lane >> 4) << 3;
    const int b_row = ((lane >> 4) << 3) + (lane & 7), b_kh = ((lane >> 3) & 1) << 3;

    {
        int is32 = g_mask_is_i32;
        unsigned v = is32 ? (unsigned)((const int*)masks)[b * Sdim + tid]
                          : (unsigned)((const unsigned char*)masks)[b * Sdim + tid];
        msk[tid] = v ? 1 : 0;
    }

    float acc[2][8][4];
#pragma unroll
    for (int i = 0; i < 2; i++)
#pragma unroll
        for (int j = 0; j < 8; j++)
#pragma unroll
            for (int r = 0; r < 4; r++) acc[i][j][r] = 0.f;

    if (tid < 256) {
        int r = tid >> 2, c = (tid & 3) * 8;
        cp16(sbA + (uint32_t)(r * RS + c) * 2u, E + (size_t)(m0 + r) * Hdim + c);
    }
#pragma unroll
    for (int i = 0; i < 4; i++) {
        int idx = tid + i * 512;
        int r = idx >> 2, c = (idx & 3) * 8;
        cp16(sbB + (uint32_t)(r * RS + c) * 2u, Bt + (size_t)r * Hdim + c);
    }
    cp_commit();

    const int KT = Hdim / 32;  // 24
#pragma unroll 1
    for (int kt = 0; kt < KT; ++kt) {
        int cur = kt & 1;
        if (kt + 1 < KT) {
            int nxt = cur ^ 1;
            if (tid < 256) {
                int r = tid >> 2, c = (tid & 3) * 8;
                cp16(sbA + (uint32_t)(nxt * 64 * RS + r * RS + c) * 2u,
                     E + (size_t)(m0 + r) * Hdim + (kt + 1) * 32 + c);
            }
#pragma unroll
            for (int i = 0; i < 4; i++) {
                int idx = tid + i * 512;
                int r = idx >> 2, c = (idx & 3) * 8;
                cp16(sbB + (uint32_t)(nxt * 512 * RS + r * RS + c) * 2u,
                     Bt + (size_t)r * Hdim + (kt + 1) * 32 + c);
            }
            cp_commit();
            cp_wait1();
        } else {
            cp_wait0();
        }
        __syncthreads();
        const uint32_t aBase = sbA + (uint32_t)(cur * 64 * RS) * 2u;
        const uint32_t bBase = sbB + (uint32_t)(cur * 512 * RS) * 2u;
#pragma unroll
        for (int kk = 0; kk < 2; ++kk) {
            uint32_t af[2][4], bf[8][2];
#pragma unroll
            for (int mt = 0; mt < 2; ++mt)
                ldsm_x4(af[mt][0], af[mt][1], af[mt][2], af[mt][3],
                        aBase + (uint32_t)(((wm * 32 + mt * 16 + a_row) * RS + kk * 16 + a_kh) * 2));
#pragma unroll
            for (int p = 0; p < 4; ++p)
                ldsm_x4(bf[2 * p][0], bf[2 * p][1], bf[2 * p + 1][0], bf[2 * p + 1][1],
                        bBase + (uint32_t)(((wn * 64 + p * 16 + b_row) * RS + kk * 16 + b_kh) * 2));
#pragma unroll
            for (int mt = 0; mt < 2; ++mt)
#pragma unroll
                for (int nt = 0; nt < 8; ++nt)
                    mma_f16(acc[mt][nt], af[mt], bf[nt]);
        }
        __syncthreads();
    }

    // ---- masked softmax epilogue (fp32) ----
    float mx[4] = {-1e30f, -1e30f, -1e30f, -1e30f};
#pragma unroll
    for (int mt = 0; mt < 2; ++mt)
#pragma unroll
        for (int nt = 0; nt < 8; ++nt) {
            int col = wn * 64 + nt * 8 + tg * 2;
            bool m0ok = msk[col] != 0, m1ok = msk[col + 1] != 0;
            if (!m0ok) { acc[mt][nt][0] = -1e30f; acc[mt][nt][2] = -1e30f; }
            if (!m1ok) { acc[mt][nt][1] = -1e30f; acc[mt][nt][3] = -1e30f; }
            mx[mt * 2]     = fmaxf(mx[mt * 2],     fmaxf(acc[mt][nt][0], acc[mt][nt][1]));
            mx[mt * 2 + 1] = fmaxf(mx[mt * 2 + 1], fmaxf(acc[mt][nt][2], acc[mt][nt][3]));
        }
#pragma unroll
    for (int j = 0; j < 4; ++j) {
        mx[j] = fmaxf(mx[j], __shfl_xor_sync(0xffffffffu, mx[j], 1));
        mx[j] = fmaxf(mx[j], __shfl_xor_sync(0xffffffffu, mx[j], 2));
    }
    if (tg == 0) {
#pragma unroll
        for (int j = 0; j < 4; ++j) {
            int rl = wm * 32 + (j >> 1) * 16 + (j & 1) * 8 + gid;
            red[rl * 8 + wn] = mx[j];
        }
    }
    __syncthreads();
    float gmx[4];
#pragma unroll
    for (int j = 0; j < 4; ++j) {
        int rl = wm * 32 + (j >> 1) * 16 + (j & 1) * 8 + gid;
        float m = -1e30f;
#pragma unroll
        for (int w = 0; w < 8; ++w) m = fmaxf(m, red[rl * 8 + w]);
        gmx[j] = m;
    }
    __syncthreads();

    float sme[4] = {0.f, 0.f, 0.f, 0.f};
#pragma unroll
    for (int mt = 0; mt < 2; ++mt)
#pragma unroll
        for (int nt = 0; nt < 8; ++nt) {
            float e0 = __expf(acc[mt][nt][0] - gmx[mt * 2]);
            float e1 = __expf(acc[mt][nt][1] - gmx[mt * 2]);
            float e2 = __expf(acc[mt][nt][2] - gmx[mt * 2 + 1]);
            float e3 = __expf(acc[mt][nt][3] - gmx[mt * 2 + 1]);
            acc[mt][nt][0] = e0; acc[mt][nt][1] = e1;
            acc[mt][nt][2] = e2; acc[mt][nt][3] = e3;
            sme[mt * 2]     += e0 + e1;
            sme[mt * 2 + 1] += e2 + e3;
        }
#pragma unroll
    for (int j = 0; j < 4; ++j) {
        sme[j] += __shfl_xor_sync(0xffffffffu, sme[j], 1);
        sme[j] += __shfl_xor_sync(0xffffffffu, sme[j], 2);
    }
    if (tg == 0) {
#pragma unroll
        for (int j = 0; j < 4; ++j) {
            int rl = wm * 32 + (j >> 1) * 16 + (j & 1) * 8 + gid;
            red[rl * 8 + wn] = sme[j];
        }
    }
    __syncthreads();
    float inv[4];
#pragma unroll
    for (int j = 0; j < 4; ++j) {
        int rl = wm * 32 + (j >> 1) * 16 + (j & 1) * 8 + gid;
        float s = 0.f;
#pragma unroll
        for (int w = 0; w < 8; ++w) s += red[rl * 8 + w];
        inv[j] = 1.f / s;
    }

    // store probs as fp16
#pragma unroll
    for (int mt = 0; mt < 2; ++mt) {
        int r = m0 + wm * 32 + mt * 16 + gid;
        size_t base0 = ((size_t)b * Ldim + r) * Sdim;
        size_t base1 = ((size_t)b * Ldim + r + 8) * Sdim;
#pragma unroll
        for (int nt = 0; nt < 8; ++nt) {
            int col = wn * 64 + nt * 8 + tg * 2;
            *(__half2*)(&g_ph[base0 + col]) =
                __floats2half2_rn(acc[mt][nt][0] * inv[mt * 2], acc[mt][nt][1] * inv[mt * 2]);
            *(__half2*)(&g_ph[base1 + col]) =
                __floats2half2_rn(acc[mt][nt][2] * inv[mt * 2 + 1], acc[mt][nt][3] * inv[mt * 2 + 1]);
        }
    }
}

// ---------------- Kernel 3: out = probs @ inputs ----------------
// BM=128 BN=128 BK=32, 256 threads (warps 2x4)
__global__ __launch_bounds__(256) void k_out(const __half* __restrict__ XT,
                                             float* __restrict__ O) {
    extern __shared__ __align__(16) float smem[];
    uint32_t sb  = (uint32_t)__cvta_generic_to_shared(smem);
    const uint32_t sbA = sb;
    const uint32_t sbB = sb + 2u * 128u * RS * 2u;

    const int tid  = threadIdx.x;
    const int lane = tid & 31, wid = tid >> 5;
    const int wm = wid & 1, wn = wid >> 1;
    const int tg = lane & 3, gid = lane >> 2;
    const int bb = blockIdx.z;
    const int m0 = blockIdx.y * 128, n0 = blockIdx.x * 128;
    const __half* gA = g_ph + ((size_t)bb * Ldim + m0) * Sdim;
    const __half* gB = XT + ((size_t)bb * Hdim + n0) * Sdim;

    const int a_row = lane & 15, a_kh = (lane >> 4) << 3;
    const int b_row = ((lane >> 4) << 3) + (lane & 7), b_kh = ((lane >> 3) & 1) << 3;

    float acc[4][4][4];
#pragma unroll
    for (int i = 0; i < 4; i++)
#pragma unroll
        for (int j = 0; j < 4; j++)
#pragma unroll
            for (int r = 0; r < 4; r++) acc[i][j][r] = 0.f;

#pragma unroll
    for (int i = 0; i < 2; i++) {
        int idx = tid + i * 256;
        int r = idx >> 2, c = (idx & 3) * 8;
        cp16(sbA + (uint32_t)(r * RS + c) * 2u, gA + (size_t)r * Sdim + c);
        cp16(sbB + (uint32_t)(r * RS + c) * 2u, gB + (size_t)r * Sdim + c);
    }
    cp_commit();

    const int KT = Sdim / 32;  // 16
#pragma unroll 1
    for (int kt = 0; kt < KT; ++kt) {
        int cur = kt & 1;
        if (kt + 1 < KT) {
            int nxt = cur ^ 1;
#pragma unroll
            for (int i = 0; i < 2; i++) {
                int idx = tid + i * 256;
                int r = idx >> 2, c = (idx & 3) * 8;
                cp16(sbA + (uint32_t)(nxt * 128 * RS + r * RS + c) * 2u,
                     gA + (size_t)r * Sdim + (kt + 1) * 32 + c);
                cp16(sbB + (uint32_t)(nxt * 128 * RS + r * RS + c) * 2u,
                     gB + (size_t)r * Sdim + (kt + 1) * 32 + c);
            }
            cp_commit();
            cp_wait1();
        } else {
            cp_wait0();
        }
        __syncthreads();
        const uint32_t aBase = sbA + (uint32_t)(cur * 128 * RS) * 2u;
        const uint32_t bBase = sbB + (uint32_t)(cur * 128 * RS) * 2u;
#pragma unroll
        for (int kk = 0; kk < 2; ++kk) {
            uint32_t af[4][4], bf[4][2];
#pragma unroll
            for (int mt = 0; mt < 4; ++mt)
                ldsm_x4(af[mt][0], af[mt][1], af[mt][2], af[mt][3],
                        aBase + (uint32_t)(((wm * 64 + mt * 16 + a_row) * RS + kk * 16 + a_kh) * 2));
#pragma unroll
            for (int p = 0; p < 2; ++p)
                ldsm_x4(bf[2 * p][0], bf[2 * p][1], bf[2 * p + 1][0], bf[2 * p + 1][1],
                        bBase + (uint32_t)(((wn * 32 + p * 16 + b_row) * RS + kk * 16 + b_kh) * 2));
#pragma unroll
            for (int mt = 0; mt < 4; ++mt)
#pragma unroll
                for (int nt = 0; nt < 4; ++nt)
                    mma_f16(acc[mt][nt], af[mt], bf[nt]);
        }
        __syncthreads();
    }
#pragma unroll
    for (int mt = 0; mt < 4; ++mt) {
        int r = m0 + wm * 64 + mt * 16 + gid;
        size_t base0 = (size_t)bb * Ldim * Hdim + (size_t)r * Hdim;
        size_t base1 = (size_t)bb * Ldim * Hdim + (size_t)(r + 8) * Hdim;
#pragma unroll
        for (int nt = 0; nt < 4; ++nt) {
            int c = n0 + wn * 32 + nt * 8 + tg * 2;
            *(float2*)(&O[base0 + c]) = make_float2(acc[mt][nt][0], acc[mt][nt][1]);
            *(float2*)(&O[base1 + c]) = make_float2(acc[mt][nt][2], acc[mt][nt][3]);
        }
    }
}

// ---------------- launcher ----------------
#define K1_SMEM_BYTES (4 * 128 * RS * 2)
#define K3_SMEM_BYTES (4 * 128 * RS * 2)

extern "C" void kernel_launch(void* const* d_in, const int* in_sizes, int n_in,
                              void* d_out, int out_size) {
    const float* inputs = (const float*)d_in[0];
    const void*  masks  = d_in[1];
    const float* emb    = (const float*)d_in[2];
    const float* wkey   = (const float*)d_in[3];
    float* out = (float*)d_out;
    (void)in_sizes; (void)n_in; (void)out_size;

    cudaFuncSetAttribute(k_keyproj, cudaFuncAttributeMaxDynamicSharedMemorySize, K1_SMEM_BYTES);
    cudaFuncSetAttribute(k_scores,  cudaFuncAttributeMaxDynamicSharedMemorySize, K2_SMEM_BYTES);
    cudaFuncSetAttribute(k_out,     cudaFuncAttributeMaxDynamicSharedMemorySize, K3_SMEM_BYTES);

    __half* d_xh;  cudaGetSymbolAddress((void**)&d_xh,  g_xh);
    __half* d_xth; cudaGetSymbolAddress((void**)&d_xth, g_xth);
    __half* d_eh;  cudaGetSymbolAddress((void**)&d_eh,  g_eh);
    __half* d_wh;  cudaGetSymbolAddress((void**)&d_wh,  g_wh);

    k_detect<<<1, 256>>>((const int*)masks);
    k_cvt<<<512, 256>>>((const float4*)inputs, (uint4*)d_xh, Bdim * Sdim * Hdim / 8);
    k_cvt<<<512, 256>>>((const float4*)emb,    (uint4*)d_eh, Ldim * Hdim / 8);
    k_cvt<<<256, 256>>>((const float4*)wkey,   (uint4*)d_wh, Hdim * Hdim / 8);
    k_trh<<<dim3(Hdim / 32, Sdim / 32, Bdim), dim3(32, 8)>>>(inputs, d_xth);
    k_keyproj<<<dim3(6, 32, 1), 256, K1_SMEM_BYTES>>>(d_xh, d_wh);
    k_scores<<<dim3(Ldim / 64, Bdim, 1), 512, K2_SMEM_BYTES>>>(d_eh, masks);
    k_out<<<dim3(6, Ldim / 128, Bdim), 256, K3_SMEM_BYTES>>>(d_xth, out);
}

// round 7
// speedup vs baseline: 1.9494x; 1.0756x over previous
#include <cuda_runtime.h>
#include <cuda_fp16.h>
#include <cstdint>

#define Bdim 8
#define Sdim 512
#define Hdim 768
#define Ldim 8192

// scratch (static device globals: allocation-free)
__device__ __half g_xh[Bdim * Sdim * Hdim];                 // inputs as fp16
__device__ __half g_xth[Bdim * Hdim * Sdim];                // inputs^T [B,H,S] fp16
__device__ __half g_eh[Ldim * Hdim];                        // label_embedding fp16
__device__ __half g_wh[Hdim * Hdim];                        // W_key fp16
__device__ __half g_akh[Bdim * Sdim * Hdim];                // attn_key fp16
__device__ __half g_ph[(size_t)Bdim * Ldim * Sdim];         // probs fp16 (67 MB)
__device__ int    g_mask_is_i32;

// ---------------- PTX helpers ----------------
__device__ __forceinline__ void mma_f16(float* c, const uint32_t* a, const uint32_t* b) {
    asm volatile(
        "mma.sync.aligned.m16n8k16.row.col.f32.f16.f16.f32 "
        "{%0,%1,%2,%3}, {%4,%5,%6,%7}, {%8,%9}, {%0,%1,%2,%3};\n"
        : "+f"(c[0]), "+f"(c[1]), "+f"(c[2]), "+f"(c[3])
        : "r"(a[0]), "r"(a[1]), "r"(a[2]), "r"(a[3]), "r"(b[0]), "r"(b[1]));
}

__device__ __forceinline__ void ldsm_x4(uint32_t& r0, uint32_t& r1, uint32_t& r2,
                                        uint32_t& r3, uint32_t addr) {
    asm volatile("ldmatrix.sync.aligned.m8n8.x4.shared.b16 {%0,%1,%2,%3}, [%4];"
                 : "=r"(r0), "=r"(r1), "=r"(r2), "=r"(r3) : "r"(addr));
}

__device__ __forceinline__ void cp16(uint32_t s, const void* g) {
    asm volatile("cp.async.cg.shared.global [%0], [%1], 16;\n" :: "r"(s), "l"(g));
}
__device__ __forceinline__ void cp_commit() { asm volatile("cp.async.commit_group;\n"); }
__device__ __forceinline__ void cp_wait1()  { asm volatile("cp.async.wait_group 1;\n"); }
__device__ __forceinline__ void cp_wait0()  { asm volatile("cp.async.wait_group 0;\n"); }

// ---------------- prep: fp32 -> fp16 ----------------
__global__ void k_cvt(const float4* __restrict__ src, uint4* __restrict__ dst, int n8) {
    int i = blockIdx.x * blockDim.x + threadIdx.x;
    int stride = gridDim.x * blockDim.x;
    for (; i < n8; i += stride) {
        float4 a = src[2 * i], b = src[2 * i + 1];
        __half2 h0 = __floats2half2_rn(a.x, a.y);
        __half2 h1 = __floats2half2_rn(a.z, a.w);
        __half2 h2 = __floats2half2_rn(b.x, b.y);
        __half2 h3 = __floats2half2_rn(b.z, b.w);
        uint4 o;
        o.x = *(uint32_t*)&h0; o.y = *(uint32_t*)&h1;
        o.z = *(uint32_t*)&h2; o.w = *(uint32_t*)&h3;
        dst[i] = o;
    }
}

// transpose+convert: XT[b][h][s] = half(X[b][s][h])
__global__ void k_trh(const float* __restrict__ X, __half* __restrict__ XT) {
    __shared__ float t[32][33];
    int b = blockIdx.z;
    int s0 = blockIdx.y * 32, h0 = blockIdx.x * 32;
    int x = threadIdx.x, y = threadIdx.y;  // 32 x 8
    const float* src = X + ((size_t)b * Sdim + s0) * Hdim + h0;
#pragma unroll
    for (int i = 0; i < 32; i += 8)
        t[y + i][x] = src[(size_t)(y + i) * Hdim + x];
    __syncthreads();
    __half* dst = XT + ((size_t)b * Hdim + h0) * Sdim + s0;
#pragma unroll
    for (int i = 0; i < 32; i += 8)
        dst[(size_t)(y + i) * Sdim + x] = __float2half_rn(t[x][y + i]);
}

// ---------------- mask dtype detection ----------------
__global__ void k_detect(const int* __restrict__ m) {
    __shared__ int bad;
    if (threadIdx.x == 0) bad = 0;
    __syncthreads();
    int local = 0;
#pragma unroll
    for (int i = 0; i < 4; i++) {
        unsigned v = (unsigned)m[threadIdx.x + i * 256];
        if (v > 1u) local = 1;
    }
    if (local) atomicOr(&bad, 1);
    __syncthreads();
    if (threadIdx.x == 0) g_mask_is_i32 = bad ? 0 : 1;
}

// Row stride in halves (80B): LDSM rows hit distinct 16B segs mod 128 -> conflict-free
#define RS 40

// ---------------- Kernel 1: attn_key = inputs @ W_key^T ----------------
// BM=128 BN=128 BK=32, 256 threads (warps 2x4, WM=64 WN=32), 2-stage
__global__ __launch_bounds__(256) void k_keyproj(const __half* __restrict__ A,
                                                 const __half* __restrict__ W) {
    extern __shared__ __align__(16) float smem[];
    uint32_t sb  = (uint32_t)__cvta_generic_to_shared(smem);
    const uint32_t sbA = sb;
    const uint32_t sbB = sb + 2u * 128u * RS * 2u;

    const int tid  = threadIdx.x;
    const int lane = tid & 31, wid = tid >> 5;
    const int wm = wid & 1, wn = wid >> 1;
    const int tg = lane & 3, gid = lane >> 2;
    const int m0 = blockIdx.y * 128, n0 = blockIdx.x * 128;

    const int a_row = lane & 15, a_kh = (lane >> 4) << 3;
    const int b_row = ((lane >> 4) << 3) + (lane & 7), b_kh = ((lane >> 3) & 1) << 3;

    float acc[4][4][4];
#pragma unroll
    for (int i = 0; i < 4; i++)
#pragma unroll
        for (int j = 0; j < 4; j++)
#pragma unroll
            for (int r = 0; r < 4; r++) acc[i][j][r] = 0.f;

#pragma unroll
    for (int i = 0; i < 2; i++) {
        int idx = tid + i * 256;
        int r = idx >> 2, c = (idx & 3) * 8;
        cp16(sbA + (uint32_t)(r * RS + c) * 2u, A + (size_t)(m0 + r) * Hdim + c);
        cp16(sbB + (uint32_t)(r * RS + c) * 2u, W + (size_t)(n0 + r) * Hdim + c);
    }
    cp_commit();

    const int KT = Hdim / 32;  // 24
#pragma unroll 1
    for (int kt = 0; kt < KT; ++kt) {
        int cur = kt & 1;
        if (kt + 1 < KT) {
            int nxt = cur ^ 1;
#pragma unroll
            for (int i = 0; i < 2; i++) {
                int idx = tid + i * 256;
                int r = idx >> 2, c = (idx & 3) * 8;
                cp16(sbA + (uint32_t)(nxt * 128 * RS + r * RS + c) * 2u,
                     A + (size_t)(m0 + r) * Hdim + (kt + 1) * 32 + c);
                cp16(sbB + (uint32_t)(nxt * 128 * RS + r * RS + c) * 2u,
                     W + (size_t)(n0 + r) * Hdim + (kt + 1) * 32 + c);
            }
            cp_commit();
            cp_wait1();
        } else {
            cp_wait0();
        }
        __syncthreads();
        const uint32_t aBase = sbA + (uint32_t)(cur * 128 * RS) * 2u;
        const uint32_t bBase = sbB + (uint32_t)(cur * 128 * RS) * 2u;
#pragma unroll
        for (int kk = 0; kk < 2; ++kk) {
            uint32_t af[4][4], bf[4][2];
#pragma unroll
            for (int mt = 0; mt < 4; ++mt)
                ldsm_x4(af[mt][0], af[mt][1], af[mt][2], af[mt][3],
                        aBase + (uint32_t)(((wm * 64 + mt * 16 + a_row) * RS + kk * 16 + a_kh) * 2));
#pragma unroll
            for (int p = 0; p < 2; ++p)
                ldsm_x4(bf[2 * p][0], bf[2 * p][1], bf[2 * p + 1][0], bf[2 * p + 1][1],
                        bBase + (uint32_t)(((wn * 32 + p * 16 + b_row) * RS + kk * 16 + b_kh) * 2));
#pragma unroll
            for (int mt = 0; mt < 4; ++mt)
#pragma unroll
                for (int nt = 0; nt < 4; ++nt)
                    mma_f16(acc[mt][nt], af[mt], bf[nt]);
        }
        __syncthreads();
    }
#pragma unroll
    for (int mt = 0; mt < 4; ++mt) {
        int r = m0 + wm * 64 + mt * 16 + gid;
#pragma unroll
        for (int nt = 0; nt < 4; ++nt) {
            int c = n0 + wn * 32 + nt * 8 + tg * 2;
            *(__half2*)(&g_akh[(size_t)r * Hdim + c]) =
                __floats2half2_rn(acc[mt][nt][0], acc[mt][nt][1]);
            *(__half2*)(&g_akh[(size_t)(r + 8) * Hdim + c]) =
                __floats2half2_rn(acc[mt][nt][2], acc[mt][nt][3]);
        }
    }
}

// ---------------- Kernel 2: probs = softmax(mask(E @ attn_key[b]^T)) --------
// BM=64 BN=512 BK=32, 512 threads (warps 2x8, WM=32 WN=64), 3-stage 1-barrier
#define K2_ASTG (64 * RS)
#define K2_BSTG (512 * RS)
#define K2_OFF_B   (3 * K2_ASTG)
#define K2_OFF_RED (K2_OFF_B + 3 * K2_BSTG)
#define K2_SMEM_BYTES ((K2_OFF_RED) * 2 + 64 * 8 * 4 + 512 + 256)

__global__ __launch_bounds__(512) void k_scores(const __half* __restrict__ E,
                                                const void* __restrict__ masks) {
    extern __shared__ __align__(16) float smem[];
    float* red = (float*)((char*)smem + (size_t)K2_OFF_RED * 2);
    unsigned char* msk = (unsigned char*)red + 64 * 8 * 4;
    uint32_t sb  = (uint32_t)__cvta_generic_to_shared(smem);
    const uint32_t sbA = sb;
    const uint32_t sbB = sb + (uint32_t)K2_OFF_B * 2u;

    const int tid  = threadIdx.x;
    const int lane = tid & 31, wid = tid >> 5;
    const int wm = wid & 1, wn = wid >> 1;  // 2 x 8
    const int tg = lane & 3, gid = lane >> 2;
    const int b  = blockIdx.y;
    const int m0 = blockIdx.x * 64;
    const __half* Bt = g_akh + (size_t)b * Sdim * Hdim;

    const int a_row = lane & 15, a_kh = (lane >> 4) << 3;
    const int b_row = ((lane >> 4) << 3) + (lane & 7), b_kh = ((lane >> 3) & 1) << 3;

    {
        int is32 = g_mask_is_i32;
        unsigned v = is32 ? (unsigned)((const int*)masks)[b * Sdim + tid]
                          : (unsigned)((const unsigned char*)masks)[b * Sdim + tid];
        msk[tid] = v ? 1 : 0;
    }

    float acc[2][8][4];
#pragma unroll
    for (int i = 0; i < 2; i++)
#pragma unroll
        for (int j = 0; j < 8; j++)
#pragma unroll
            for (int r = 0; r < 4; r++) acc[i][j][r] = 0.f;

    auto fill = [&](int st, int kt) {
        if (tid < 256) {
            int r = tid >> 2, c = (tid & 3) * 8;
            cp16(sbA + (uint32_t)(st * K2_ASTG + r * RS + c) * 2u,
                 E + (size_t)(m0 + r) * Hdim + kt * 32 + c);
        }
#pragma unroll
        for (int i = 0; i < 4; i++) {
            int idx = tid + i * 512;
            int r = idx >> 2, c = (idx & 3) * 8;
            cp16(sbB + (uint32_t)(st * K2_BSTG + r * RS + c) * 2u,
                 Bt + (size_t)r * Hdim + kt * 32 + c);
        }
        cp_commit();
    };

    const int KT = Hdim / 32;  // 24
    fill(0, 0);
    fill(1, 1);
    cp_wait1();
    __syncthreads();

#pragma unroll 1
    for (int kt = 0; kt < KT; ++kt) {
        int cur = kt % 3;
        const uint32_t aBase = sbA + (uint32_t)(cur * K2_ASTG) * 2u;
        const uint32_t bBase = sbB + (uint32_t)(cur * K2_BSTG) * 2u;
#pragma unroll
        for (int kk = 0; kk < 2; ++kk) {
            uint32_t af[2][4], bf[8][2];
#pragma unroll
            for (int mt = 0; mt < 2; ++mt)
                ldsm_x4(af[mt][0], af[mt][1], af[mt][2], af[mt][3],
                        aBase + (uint32_t)(((wm * 32 + mt * 16 + a_row) * RS + kk * 16 + a_kh) * 2));
#pragma unroll
            for (int p = 0; p < 4; ++p)
                ldsm_x4(bf[2 * p][0], bf[2 * p][1], bf[2 * p + 1][0], bf[2 * p + 1][1],
                        bBase + (uint32_t)(((wn * 64 + p * 16 + b_row) * RS + kk * 16 + b_kh) * 2));
#pragma unroll
            for (int mt = 0; mt < 2; ++mt)
#pragma unroll
                for (int nt = 0; nt < 8; ++nt)
                    mma_f16(acc[mt][nt], af[mt], bf[nt]);
        }
        if (kt + 2 < KT) fill((kt + 2) % 3, kt + 2);
        if (kt + 1 < KT) { if (kt + 2 < KT) cp_wait1(); else cp_wait0(); }
        __syncthreads();
    }

    // ---- masked softmax epilogue (fp32) ----
    float mx[4] = {-1e30f, -1e30f, -1e30f, -1e30f};
#pragma unroll
    for (int mt = 0; mt < 2; ++mt)
#pragma unroll
        for (int nt = 0; nt < 8; ++nt) {
            int col = wn * 64 + nt * 8 + tg * 2;
            bool m0ok = msk[col] != 0, m1ok = msk[col + 1] != 0;
            if (!m0ok) { acc[mt][nt][0] = -1e30f; acc[mt][nt][2] = -1e30f; }
            if (!m1ok) { acc[mt][nt][1] = -1e30f; acc[mt][nt][3] = -1e30f; }
            mx[mt * 2]     = fmaxf(mx[mt * 2],     fmaxf(acc[mt][nt][0], acc[mt][nt][1]));
            mx[mt * 2 + 1] = fmaxf(mx[mt * 2 + 1], fmaxf(acc[mt][nt][2], acc[mt][nt][3]));
        }
#pragma unroll
    for (int j = 0; j < 4; ++j) {
        mx[j] = fmaxf(mx[j], __shfl_xor_sync(0xffffffffu, mx[j], 1));
        mx[j] = fmaxf(mx[j], __shfl_xor_sync(0xffffffffu, mx[j], 2));
    }
    if (tg == 0) {
#pragma unroll
        for (int j = 0; j < 4; ++j) {
            int rl = wm * 32 + (j >> 1) * 16 + (j & 1) * 8 + gid;
            red[rl * 8 + wn] = mx[j];
        }
    }
    __syncthreads();
    float gmx[4];
#pragma unroll
    for (int j = 0; j < 4; ++j) {
        int rl = wm * 32 + (j >> 1) * 16 + (j & 1) * 8 + gid;
        float m = -1e30f;
#pragma unroll
        for (int w = 0; w < 8; ++w) m = fmaxf(m, red[rl * 8 + w]);
        gmx[j] = m;
    }
    __syncthreads();

    float sme[4] = {0.f, 0.f, 0.f, 0.f};
#pragma unroll
    for (int mt = 0; mt < 2; ++mt)
#pragma unroll
        for (int nt = 0; nt < 8; ++nt) {
            float e0 = __expf(acc[mt][nt][0] - gmx[mt * 2]);
            float e1 = __expf(acc[mt][nt][1] - gmx[mt * 2]);
            float e2 = __expf(acc[mt][nt][2] - gmx[mt * 2 + 1]);
            float e3 = __expf(acc[mt][nt][3] - gmx[mt * 2 + 1]);
            acc[mt][nt][0] = e0; acc[mt][nt][1] = e1;
            acc[mt][nt][2] = e2; acc[mt][nt][3] = e3;
            sme[mt * 2]     += e0 + e1;
            sme[mt * 2 + 1] += e2 + e3;
        }
#pragma unroll
    for (int j = 0; j < 4; ++j) {
        sme[j] += __shfl_xor_sync(0xffffffffu, sme[j], 1);
        sme[j] += __shfl_xor_sync(0xffffffffu, sme[j], 2);
    }
    if (tg == 0) {
#pragma unroll
        for (int j = 0; j < 4; ++j) {
            int rl = wm * 32 + (j >> 1) * 16 + (j & 1) * 8 + gid;
            red[rl * 8 + wn] = sme[j];
        }
    }
    __syncthreads();
    float inv[4];
#pragma unroll
    for (int j = 0; j < 4; ++j) {
        int rl = wm * 32 + (j >> 1) * 16 + (j & 1) * 8 + gid;
        float s = 0.f;
#pragma unroll
        for (int w = 0; w < 8; ++w) s += red[rl * 8 + w];
        inv[j] = 1.f / s;
    }

    // store probs as fp16
#pragma unroll
    for (int mt = 0; mt < 2; ++mt) {
        int r = m0 + wm * 32 + mt * 16 + gid;
        size_t base0 = ((size_t)b * Ldim + r) * Sdim;
        size_t base1 = ((size_t)b * Ldim + r + 8) * Sdim;
#pragma unroll
        for (int nt = 0; nt < 8; ++nt) {
            int col = wn * 64 + nt * 8 + tg * 2;
            *(__half2*)(&g_ph[base0 + col]) =
                __floats2half2_rn(acc[mt][nt][0] * inv[mt * 2], acc[mt][nt][1] * inv[mt * 2]);
            *(__half2*)(&g_ph[base1 + col]) =
                __floats2half2_rn(acc[mt][nt][2] * inv[mt * 2 + 1], acc[mt][nt][3] * inv[mt * 2 + 1]);
        }
    }
}

// ---------------- Kernel 3: out = probs @ inputs ----------------
// BM=128 BN=256 BK=32, 256 threads (warps 2x4, WM=64 WN=64), 3-stage 1-barrier
#define K3_ASTG (128 * RS)
#define K3_BSTG (256 * RS)
#define K3_SMEM_BYTES ((3 * K3_ASTG + 3 * K3_BSTG) * 2)

__global__ __launch_bounds__(256) void k_out(const __half* __restrict__ XT,
                                             float* __restrict__ O) {
    extern __shared__ __align__(16) float smem[];
    uint32_t sb  = (uint32_t)__cvta_generic_to_shared(smem);
    const uint32_t sbA = sb;
    const uint32_t sbB = sb + 3u * K3_ASTG * 2u;

    const int tid  = threadIdx.x;
    const int lane = tid & 31, wid = tid >> 5;
    const int wm = wid & 1, wn = wid >> 1;  // 2 x 4
    const int tg = lane & 3, gid = lane >> 2;
    const int bb = blockIdx.z;
    const int m0 = blockIdx.y * 128, n0 = blockIdx.x * 256;
    const __half* gA = g_ph + ((size_t)bb * Ldim + m0) * Sdim;
    const __half* gB = XT + ((size_t)bb * Hdim + n0) * Sdim;

    const int a_row = lane & 15, a_kh = (lane >> 4) << 3;
    const int b_row = ((lane >> 4) << 3) + (lane & 7), b_kh = ((lane >> 3) & 1) << 3;

    float acc[4][8][4];
#pragma unroll
    for (int i = 0; i < 4; i++)
#pragma unroll
        for (int j = 0; j < 8; j++)
#pragma unroll
            for (int r = 0; r < 4; r++) acc[i][j][r] = 0.f;

    auto fill = [&](int st, int kt) {
#pragma unroll
        for (int i = 0; i < 2; i++) {
            int idx = tid + i * 256;
            int r = idx >> 2, c = (idx & 3) * 8;
            cp16(sbA + (uint32_t)(st * K3_ASTG + r * RS + c) * 2u,
                 gA + (size_t)r * Sdim + kt * 32 + c);
        }
#pragma unroll
        for (int i = 0; i < 4; i++) {
            int idx = tid + i * 256;
            int r = idx >> 2, c = (idx & 3) * 8;
            cp16(sbB + (uint32_t)(st * K3_BSTG + r * RS + c) * 2u,
                 gB + (size_t)r * Sdim + kt * 32 + c);
        }
        cp_commit();
    };

    const int KT = Sdim / 32;  // 16
    fill(0, 0);
    fill(1, 1);
    cp_wait1();
    __syncthreads();

#pragma unroll 1
    for (int kt = 0; kt < KT; ++kt) {
        int cur = kt % 3;
        const uint32_t aBase = sbA + (uint32_t)(cur * K3_ASTG) * 2u;
        const uint32_t bBase = sbB + (uint32_t)(cur * K3_BSTG) * 2u;
#pragma unroll
        for (int kk = 0; kk < 2; ++kk) {
            uint32_t af[4][4], bf[8][2];
#pragma unroll
            for (int mt = 0; mt < 4; ++mt)
                ldsm_x4(af[mt][0], af[mt][1], af[mt][2], af[mt][3],
                        aBase + (uint32_t)(((wm * 64 + mt * 16 + a_row) * RS + kk * 16 + a_kh) * 2));
#pragma unroll
            for (int p = 0; p < 4; ++p)
                ldsm_x4(bf[2 * p][0], bf[2 * p][1], bf[2 * p + 1][0], bf[2 * p + 1][1],
                        bBase + (uint32_t)(((wn * 64 + p * 16 + b_row) * RS + kk * 16 + b_kh) * 2));
#pragma unroll
            for (int mt = 0; mt < 4; ++mt)
#pragma unroll
                for (int nt = 0; nt < 8; ++nt)
                    mma_f16(acc[mt][nt], af[mt], bf[nt]);
        }
        if (kt + 2 < KT) fill((kt + 2) % 3, kt + 2);
        if (kt + 1 < KT) { if (kt + 2 < KT) cp_wait1(); else cp_wait0(); }
        __syncthreads();
    }

#pragma unroll
    for (int mt = 0; mt < 4; ++mt) {
        int r = m0 + wm * 64 + mt * 16 + gid;
        size_t base0 = (size_t)bb * Ldim * Hdim + (size_t)r * Hdim;
        size_t base1 = (size_t)bb * Ldim * Hdim + (size_t)(r + 8) * Hdim;
#pragma unroll
        for (int nt = 0; nt < 8; ++nt) {
            int c = n0 + wn * 64 + nt * 8 + tg * 2;
            *(float2*)(&O[base0 + c]) = make_float2(acc[mt][nt][0], acc[mt][nt][1]);
            *(float2*)(&O[base1 + c]) = make_float2(acc[mt][nt][2], acc[mt][nt][3]);
        }
    }
}

// ---------------- launcher ----------------
#define K1_SMEM_BYTES (4 * 128 * RS * 2)

extern "C" void kernel_launch(void* const* d_in, const int* in_sizes, int n_in,
                              void* d_out, int out_size) {
    const float* inputs = (const float*)d_in[0];
    const void*  masks  = d_in[1];
    const float* emb    = (const float*)d_in[2];
    const float* wkey   = (const float*)d_in[3];
    float* out = (float*)d_out;
    (void)in_sizes; (void)n_in; (void)out_size;

    cudaFuncSetAttribute(k_keyproj, cudaFuncAttributeMaxDynamicSharedMemorySize, K1_SMEM_BYTES);
    cudaFuncSetAttribute(k_scores,  cudaFuncAttributeMaxDynamicSharedMemorySize, K2_SMEM_BYTES);
    cudaFuncSetAttribute(k_out,     cudaFuncAttributeMaxDynamicSharedMemorySize, K3_SMEM_BYTES);

    __half* d_xh;  cudaGetSymbolAddress((void**)&d_xh,  g_xh);
    __half* d_xth; cudaGetSymbolAddress((void**)&d_xth, g_xth);
    __half* d_eh;  cudaGetSymbolAddress((void**)&d_eh,  g_eh);
    __half* d_wh;  cudaGetSymbolAddress((void**)&d_wh,  g_wh);

    k_detect<<<1, 256>>>((const int*)masks);
    k_cvt<<<512, 256>>>((const float4*)inputs, (uint4*)d_xh, Bdim * Sdim * Hdim / 8);
    k_cvt<<<512, 256>>>((const float4*)emb,    (uint4*)d_eh, Ldim * Hdim / 8);
    k_cvt<<<256, 256>>>((const float4*)wkey,   (uint4*)d_wh, Hdim * Hdim / 8);
    k_trh<<<dim3(Hdim / 32, Sdim / 32, Bdim), dim3(32, 8)>>>(inputs, d_xth);
    k_keyproj<<<dim3(6, 32, 1), 256, K1_SMEM_BYTES>>>(d_xh, d_wh);
    k_scores<<<dim3(Ldim / 64, Bdim, 1), 512, K2_SMEM_BYTES>>>(d_eh, masks);
    k_out<<<dim3(Hdim / 256, Ldim / 128, Bdim), 256, K3_SMEM_BYTES>>>(d_xth, out);
}

// round 9
// speedup vs baseline: 1.9558x; 1.0033x over previous
#include <cuda_runtime.h>
#include <cuda_fp16.h>
#include <cstdint>

#define Bdim 8
#define Sdim 512
#define Hdim 768
#define Ldim 8192

// scratch (static device globals: allocation-free)
__device__ __half g_xh[Bdim * Sdim * Hdim];                 // inputs as fp16
__device__ __half g_xth[Bdim * Hdim * Sdim];                // inputs^T [B,H,S] fp16
__device__ __half g_eh[Ldim * Hdim];                        // label_embedding fp16
__device__ __half g_wh[Hdim * Hdim];                        // W_key fp16
__device__ __half g_akh[Bdim * Sdim * Hdim];                // attn_key fp16
__device__ int    g_mask_is_i32;

// ---------------- PTX helpers ----------------
__device__ __forceinline__ void mma_f16(float* c, const uint32_t* a, const uint32_t* b) {
    asm volatile(
        "mma.sync.aligned.m16n8k16.row.col.f32.f16.f16.f32 "
        "{%0,%1,%2,%3}, {%4,%5,%6,%7}, {%8,%9}, {%0,%1,%2,%3};\n"
        : "+f"(c[0]), "+f"(c[1]), "+f"(c[2]), "+f"(c[3])
        : "r"(a[0]), "r"(a[1]), "r"(a[2]), "r"(a[3]), "r"(b[0]), "r"(b[1]));
}

__device__ __forceinline__ void ldsm_x4(uint32_t& r0, uint32_t& r1, uint32_t& r2,
                                        uint32_t& r3, uint32_t addr) {
    asm volatile("ldmatrix.sync.aligned.m8n8.x4.shared.b16 {%0,%1,%2,%3}, [%4];"
                 : "=r"(r0), "=r"(r1), "=r"(r2), "=r"(r3) : "r"(addr));
}

__device__ __forceinline__ void cp16(uint32_t s, const void* g) {
    asm volatile("cp.async.cg.shared.global [%0], [%1], 16;\n" :: "r"(s), "l"(g));
}
__device__ __forceinline__ void cp_commit() { asm volatile("cp.async.commit_group;\n"); }
__device__ __forceinline__ void cp_wait1()  { asm volatile("cp.async.wait_group 1;\n"); }
__device__ __forceinline__ void cp_wait0()  { asm volatile("cp.async.wait_group 0;\n"); }

// ---------------- prep: fp32 -> fp16 ----------------
__global__ void k_cvt(const float4* __restrict__ src, uint4* __restrict__ dst, int n8) {
    int i = blockIdx.x * blockDim.x + threadIdx.x;
    int stride = gridDim.x * blockDim.x;
    for (; i < n8; i += stride) {
        float4 a = src[2 * i], b = src[2 * i + 1];
        __half2 h0 = __floats2half2_rn(a.x, a.y);
        __half2 h1 = __floats2half2_rn(a.z, a.w);
        __half2 h2 = __floats2half2_rn(b.x, b.y);
        __half2 h3 = __floats2half2_rn(b.z, b.w);
        uint4 o;
        o.x = *(uint32_t*)&h0; o.y = *(uint32_t*)&h1;
        o.z = *(uint32_t*)&h2; o.w = *(uint32_t*)&h3;
        dst[i] = o;
    }
}

// transpose+convert: XT[b][h][s] = half(X[b][s][h])
__global__ void k_trh(const float* __restrict__ X, __half* __restrict__ XT) {
    __shared__ float t[32][33];
    int b = blockIdx.z;
    int s0 = blockIdx.y * 32, h0 = blockIdx.x * 32;
    int x = threadIdx.x, y = threadIdx.y;  // 32 x 8
    const float* src = X + ((size_t)b * Sdim + s0) * Hdim + h0;
#pragma unroll
    for (int i = 0; i < 32; i += 8)
        t[y + i][x] = src[(size_t)(y + i) * Hdim + x];
    __syncthreads();
    __half* dst = XT + ((size_t)b * Hdim + h0) * Sdim + s0;
#pragma unroll
    for (int i = 0; i < 32; i += 8)
        dst[(size_t)(y + i) * Sdim + x] = __float2half_rn(t[x][y + i]);
}

// ---------------- mask dtype detection ----------------
__global__ void k_detect(const int* __restrict__ m) {
    __shared__ int bad;
    if (threadIdx.x == 0) bad = 0;
    __syncthreads();
    int local = 0;
#pragma unroll
    for (int i = 0; i < 4; i++) {
        unsigned v = (unsigned)m[threadIdx.x + i * 256];
        if (v > 1u) local = 1;
    }
    if (local) atomicOr(&bad, 1);
    __syncthreads();
    if (threadIdx.x == 0) g_mask_is_i32 = bad ? 0 : 1;
}

// Row stride in halves (80B): LDSM rows hit distinct 16B segs mod 128 -> conflict-free
#define RS 40

// ---------------- Kernel 1: attn_key = inputs @ W_key^T ----------------
// BM=128 BN=128 BK=32, 256 threads (warps 2x4, WM=64 WN=32), 2-stage
__global__ __launch_bounds__(256) void k_keyproj(const __half* __restrict__ A,
                                                 const __half* __restrict__ W) {
    extern __shared__ __align__(16) float smem[];
    uint32_t sb  = (uint32_t)__cvta_generic_to_shared(smem);
    const uint32_t sbA = sb;
    const uint32_t sbB = sb + 2u * 128u * RS * 2u;

    const int tid  = threadIdx.x;
    const int lane = tid & 31, wid = tid >> 5;
    const int wm = wid & 1, wn = wid >> 1;
    const int tg = lane & 3, gid = lane >> 2;
    const int m0 = blockIdx.y * 128, n0 = blockIdx.x * 128;

    const int a_row = lane & 15, a_kh = (lane >> 4) << 3;
    const int b_row = ((lane >> 4) << 3) + (lane & 7), b_kh = ((lane >> 3) & 1) << 3;

    float acc[4][4][4];
#pragma unroll
    for (int i = 0; i < 4; i++)
#pragma unroll
        for (int j = 0; j < 4; j++)
#pragma unroll
            for (int r = 0; r < 4; r++) acc[i][j][r] = 0.f;

#pragma unroll
    for (int i = 0; i < 2; i++) {
        int idx = tid + i * 256;
        int r = idx >> 2, c = (idx & 3) * 8;
        cp16(sbA + (uint32_t)(r * RS + c) * 2u, A + (size_t)(m0 + r) * Hdim + c);
        cp16(sbB + (uint32_t)(r * RS + c) * 2u, W + (size_t)(n0 + r) * Hdim + c);
    }
    cp_commit();

    const int KT = Hdim / 32;  // 24
#pragma unroll 1
    for (int kt = 0; kt < KT; ++kt) {
        int cur = kt & 1;
        if (kt + 1 < KT) {
            int nxt = cur ^ 1;
#pragma unroll
            for (int i = 0; i < 2; i++) {
                int idx = tid + i * 256;
                int r = idx >> 2, c = (idx & 3) * 8;
                cp16(sbA + (uint32_t)(nxt * 128 * RS + r * RS + c) * 2u,
                     A + (size_t)(m0 + r) * Hdim + (kt + 1) * 32 + c);
                cp16(sbB + (uint32_t)(nxt * 128 * RS + r * RS + c) * 2u,
                     W + (size_t)(n0 + r) * Hdim + (kt + 1) * 32 + c);
            }
            cp_commit();
            cp_wait1();
        } else {
            cp_wait0();
        }
        __syncthreads();
        const uint32_t aBase = sbA + (uint32_t)(cur * 128 * RS) * 2u;
        const uint32_t bBase = sbB + (uint32_t)(cur * 128 * RS) * 2u;
#pragma unroll
        for (int kk = 0; kk < 2; ++kk) {
            uint32_t af[4][4], bf[4][2];
#pragma unroll
            for (int mt = 0; mt < 4; ++mt)
                ldsm_x4(af[mt][0], af[mt][1], af[mt][2], af[mt][3],
                        aBase + (uint32_t)(((wm * 64 + mt * 16 + a_row) * RS + kk * 16 + a_kh) * 2));
#pragma unroll
            for (int p = 0; p < 2; ++p)
                ldsm_x4(bf[2 * p][0], bf[2 * p][1], bf[2 * p + 1][0], bf[2 * p + 1][1],
                        bBase + (uint32_t)(((wn * 32 + p * 16 + b_row) * RS + kk * 16 + b_kh) * 2));
#pragma unroll
            for (int mt = 0; mt < 4; ++mt)
#pragma unroll
                for (int nt = 0; nt < 4; ++nt)
                    mma_f16(acc[mt][nt], af[mt], bf[nt]);
        }
        __syncthreads();
    }
#pragma unroll
    for (int mt = 0; mt < 4; ++mt) {
        int r = m0 + wm * 64 + mt * 16 + gid;
#pragma unroll
        for (int nt = 0; nt < 4; ++nt) {
            int c = n0 + wn * 32 + nt * 8 + tg * 2;
            *(__half2*)(&g_akh[(size_t)r * Hdim + c]) =
                __floats2half2_rn(acc[mt][nt][0], acc[mt][nt][1]);
            *(__half2*)(&g_akh[(size_t)(r + 8) * Hdim + c]) =
                __floats2half2_rn(acc[mt][nt][2], acc[mt][nt][3]);
        }
    }
}

// ---------------- Fused Kernel: softmax(mask(E@AK^T)) @ X ------------------
// Per CTA: 64 labels x batch b. 256 threads, warps 2x4.
// Phase 1: scores 64x512 (BK=32, 3-stage), masked softmax, probs -> smem fp16.
// Phase 2: out[64,768] = probs @ X, H split into 2x384, XT streamed 3-stage.
#define P_RS 520
#define F_ASTG (64 * RS)
#define F_BSTG (512 * RS)
#define F_B_OFF (3 * F_ASTG)
#define F_XT_OFF (64 * P_RS)
#define F_XTSTG (384 * RS)
#define F_RED_BYTE (2 * (F_XT_OFF + 3 * F_XTSTG))
#define F_SMEM_BYTES (F_RED_BYTE + 64 * 4 * 4 + 512)

__global__ __launch_bounds__(256) void k_fused(const __half* __restrict__ E,
                                               const __half* __restrict__ XT,
                                               const void* __restrict__ masks,
                                               float* __restrict__ O) {
    extern __shared__ __align__(16) float smem[];
    uint32_t sb = (uint32_t)__cvta_generic_to_shared(smem);
    float* red = (float*)((char*)smem + F_RED_BYTE);
    unsigned char* msk = (unsigned char*)red + 64 * 4 * 4;

    const int tid  = threadIdx.x;
    const int lane = tid & 31, wid = tid >> 5;
    const int wm = wid & 1, wn = wid >> 1;  // 2 x 4
    const int tg = lane & 3, gid = lane >> 2;
    const int b  = blockIdx.y;
    const int m0 = blockIdx.x * 64;
    const __half* Bt = g_akh + (size_t)b * Sdim * Hdim;

    const int a_row = lane & 15, a_kh = (lane >> 4) << 3;
    const int b_row = ((lane >> 4) << 3) + (lane & 7), b_kh = ((lane >> 3) & 1) << 3;

    {   // mask -> smem
        int is32 = g_mask_is_i32;
#pragma unroll
        for (int i = 0; i < 2; i++) {
            int s = tid + i * 256;
            unsigned v = is32 ? (unsigned)((const int*)masks)[b * Sdim + s]
                              : (unsigned)((const unsigned char*)masks)[b * Sdim + s];
            msk[s] = v ? 1 : 0;
        }
    }

    const uint32_t sbA = sb;
    const uint32_t sbB = sb + (uint32_t)F_B_OFF * 2u;

    // ================= Phase 1: scores + softmax =================
    float acc[2][16][4];
#pragma unroll
    for (int i = 0; i < 2; i++)
#pragma unroll
        for (int j = 0; j < 16; j++)
#pragma unroll
            for (int r = 0; r < 4; r++) acc[i][j][r] = 0.f;

    auto fill1 = [&](int st, int kt) {
        {   // A: 64 x 32 halves = 256 cp16
            int r = tid >> 2, c = (tid & 3) * 8;
            cp16(sbA + (uint32_t)(st * F_ASTG + r * RS + c) * 2u,
                 E + (size_t)(m0 + r) * Hdim + kt * 32 + c);
        }
#pragma unroll
        for (int i = 0; i < 8; i++) {  // B: 512 x 32 halves = 2048 cp16
            int idx = tid + i * 256;
            int r = idx >> 2, c = (idx & 3) * 8;
            cp16(sbB + (uint32_t)(st * F_BSTG + r * RS + c) * 2u,
                 Bt + (size_t)r * Hdim + kt * 32 + c);
        }
        cp_commit();
    };

    const int KT = Hdim / 32;  // 24
    fill1(0, 0);
    fill1(1, 1);
    cp_wait1();
    __syncthreads();

#pragma unroll 1
    for (int kt = 0; kt < KT; ++kt) {
        int cur = kt % 3;
        const uint32_t aBase = sbA + (uint32_t)(cur * F_ASTG) * 2u;
        const uint32_t bBase = sbB + (uint32_t)(cur * F_BSTG) * 2u;
#pragma unroll
        for (int kk = 0; kk < 2; ++kk) {
            uint32_t af[2][4], bf[16][2];
#pragma unroll
            for (int mt = 0; mt < 2; ++mt)
                ldsm_x4(af[mt][0], af[mt][1], af[mt][2], af[mt][3],
                        aBase + (uint32_t)(((wm * 32 + mt * 16 + a_row) * RS + kk * 16 + a_kh) * 2));
#pragma unroll
            for (int p = 0; p < 8; ++p)
                ldsm_x4(bf[2 * p][0], bf[2 * p][1], bf[2 * p + 1][0], bf[2 * p + 1][1],
                        bBase + (uint32_t)(((wn * 128 + p * 16 + b_row) * RS + kk * 16 + b_kh) * 2));
#pragma unroll
            for (int mt = 0; mt < 2; ++mt)
#pragma unroll
                for (int nt = 0; nt < 16; ++nt)
                    mma_f16(acc[mt][nt], af[mt], bf[nt]);
        }
        if (kt + 2 < KT) fill1((kt + 2) % 3, kt + 2);
        if (kt + 1 < KT) { if (kt + 2 < KT) cp_wait1(); else cp_wait0(); }
        __syncthreads();
    }

    // masked softmax (fp32); lane owns 4 rows: j -> wm*32 + (j>>1)*16 + (j&1)*8 + gid
    float mx[4] = {-1e30f, -1e30f, -1e30f, -1e30f};
#pragma unroll
    for (int mt = 0; mt < 2; ++mt)
#pragma unroll
        for (int nt = 0; nt < 16; ++nt) {
            int col = wn * 128 + nt * 8 + tg * 2;
            bool m0ok = msk[col] != 0, m1ok = msk[col + 1] != 0;
            if (!m0ok) { acc[mt][nt][0] = -1e30f; acc[mt][nt][2] = -1e30f; }
            if (!m1ok) { acc[mt][nt][1] = -1e30f; acc[mt][nt][3] = -1e30f; }
            mx[mt * 2]     = fmaxf(mx[mt * 2],     fmaxf(acc[mt][nt][0], acc[mt][nt][1]));
            mx[mt * 2 + 1] = fmaxf(mx[mt * 2 + 1], fmaxf(acc[mt][nt][2], acc[mt][nt][3]));
        }
#pragma unroll
    for (int j = 0; j < 4; ++j) {
        mx[j] = fmaxf(mx[j], __shfl_xor_sync(0xffffffffu, mx[j], 1));
        mx[j] = fmaxf(mx[j], __shfl_xor_sync(0xffffffffu, mx[j], 2));
    }
    if (tg == 0) {
#pragma unroll
        for (int j = 0; j < 4; ++j) {
            int rl = wm * 32 + (j >> 1) * 16 + (j & 1) * 8 + gid;
            red[rl * 4 + wn] = mx[j];
        }
    }
    __syncthreads();
    float gmx[4];
#pragma unroll
    for (int j = 0; j < 4; ++j) {
        int rl = wm * 32 + (j >> 1) * 16 + (j & 1) * 8 + gid;
        float m = -1e30f;
#pragma unroll
        for (int w = 0; w < 4; ++w) m = fmaxf(m, red[rl * 4 + w]);
        gmx[j] = m;
    }
    __syncthreads();

    float sme[4] = {0.f, 0.f, 0.f, 0.f};
#pragma unroll
    for (int mt = 0; mt < 2; ++mt)
#pragma unroll
        for (int nt = 0; nt < 16; ++nt) {
            float e0 = __expf(acc[mt][nt][0] - gmx[mt * 2]);
            float e1 = __expf(acc[mt][nt][1] - gmx[mt * 2]);
            float e2 = __expf(acc[mt][nt][2] - gmx[mt * 2 + 1]);
            float e3 = __expf(acc[mt][nt][3] - gmx[mt * 2 + 1]);
            acc[mt][nt][0] = e0; acc[mt][nt][1] = e1;
            acc[mt][nt][2] = e2; acc[mt][nt][3] = e3;
            sme[mt * 2]     += e0 + e1;
            sme[mt * 2 + 1] += e2 + e3;
        }
#pragma unroll
    for (int j = 0; j < 4; ++j) {
        sme[j] += __shfl_xor_sync(0xffffffffu, sme[j], 1);
        sme[j] += __shfl_xor_sync(0xffffffffu, sme[j], 2);
    }
    if (tg == 0) {
#pragma unroll
        for (int j = 0; j < 4; ++j) {
            int rl = wm * 32 + (j >> 1) * 16 + (j & 1) * 8 + gid;
            red[rl * 4 + wn] = sme[j];
        }
    }
    __syncthreads();
    float inv[4];
#pragma unroll
    for (int j = 0; j < 4; ++j) {
        int rl = wm * 32 + (j >> 1) * 16 + (j & 1) * 8 + gid;
        float s = 0.f;
#pragma unroll
        for (int w = 0; w < 4; ++w) s += red[rl * 4 + w];
        inv[j] = 1.f / s;
    }

    // probs -> smem fp16 (aliases dead phase-1 stages; write after loop's final barrier)
    __half* probs = (__half*)smem;
#pragma unroll
    for (int mt = 0; mt < 2; ++mt) {
        int r0 = wm * 32 + mt * 16 + gid;
        int r1 = r0 + 8;
#pragma unroll
        for (int nt = 0; nt < 16; ++nt) {
            int col = wn * 128 + nt * 8 + tg * 2;
            *(__half2*)(&probs[r0 * P_RS + col]) =
                __floats2half2_rn(acc[mt][nt][0] * inv[mt * 2], acc[mt][nt][1] * inv[mt * 2]);
            *(__half2*)(&probs[r1 * P_RS + col]) =
                __floats2half2_rn(acc[mt][nt][2] * inv[mt * 2 + 1], acc[mt][nt][3] * inv[mt * 2 + 1]);
        }
    }
    __syncthreads();

    // ================= Phase 2: out = probs @ X =================
    const uint32_t pB   = sb;                               // probs base
    const uint32_t sbXT = sb + (uint32_t)F_XT_OFF * 2u;

#pragma unroll 1
    for (int ht = 0; ht < 2; ++ht) {
        const __half* Xg = XT + ((size_t)b * Hdim + ht * 384) * Sdim;

        float acc2[2][12][4];
#pragma unroll
        for (int i = 0; i < 2; i++)
#pragma unroll
            for (int j = 0; j < 12; j++)
#pragma unroll
                for (int r = 0; r < 4; r++) acc2[i][j][r] = 0.f;

        auto fill2 = [&](int st, int kt) {
#pragma unroll
            for (int i = 0; i < 6; i++) {  // 384 x 32 halves = 1536 cp16
                int idx = tid + i * 256;
                int r = idx >> 2, c = (idx & 3) * 8;
                cp16(sbXT + (uint32_t)(st * F_XTSTG + r * RS + c) * 2u,
                     Xg + (size_t)r * Sdim + kt * 32 + c);
            }
            cp_commit();
        };

        const int KT2 = Sdim / 32;  // 16
        fill2(0, 0);
        fill2(1, 1);
        cp_wait1();
        __syncthreads();

#pragma unroll 1
        for (int kt = 0; kt < KT2; ++kt) {
            int cur = kt % 3;
            const uint32_t xBase = sbXT + (uint32_t)(cur * F_XTSTG) * 2u;
#pragma unroll
            for (int kk = 0; kk < 2; ++kk) {
                uint32_t af[2][4], bf[12][2];
#pragma unroll
                for (int mt = 0; mt < 2; ++mt)
                    ldsm_x4(af[mt][0], af[mt][1], af[mt][2], af[mt][3],
                            pB + (uint32_t)(((wm * 32 + mt * 16 + a_row) * P_RS +
                                             kt * 32 + kk * 16 + a_kh) * 2));
#pragma unroll
                for (int p = 0; p < 6; ++p)
                    ldsm_x4(bf[2 * p][0], bf[2 * p][1], bf[2 * p + 1][0], bf[2 * p + 1][1],
                            xBase + (uint32_t)(((wn * 96 + p * 16 + b_row) * RS + kk * 16 + b_kh) * 2));
#pragma unroll
                for (int mt = 0; mt < 2; ++mt)
#pragma unroll
                    for (int nt = 0; nt < 12; ++nt)
                        mma_f16(acc2[mt][nt], af[mt], bf[nt]);
            }
            if (kt + 2 < KT2) fill2((kt + 2) % 3, kt + 2);
            if (kt + 1 < KT2) { if (kt + 2 < KT2) cp_wait1(); else cp_wait0(); }
            __syncthreads();
        }

        // epilogue: write this H-half
#pragma unroll
        for (int mt = 0; mt < 2; ++mt) {
            int r = m0 + wm * 32 + mt * 16 + gid;
            size_t base0 = ((size_t)b * Ldim + r) * Hdim;
            size_t base1 = ((size_t)b * Ldim + r + 8) * Hdim;
#pragma unroll
            for (int nt = 0; nt < 12; ++nt) {
                int c = ht * 384 + wn * 96 + nt * 8 + tg * 2;
                *(float2*)(&O[base0 + c]) = make_float2(acc2[mt][nt][0], acc2[mt][nt][1]);
                *(float2*)(&O[base1 + c]) = make_float2(acc2[mt][nt][2], acc2[mt][nt][3]);
            }
        }
    }
}

// ---------------- launcher ----------------
#define K1_SMEM_BYTES (4 * 128 * RS * 2)

extern "C" void kernel_launch(void* const* d_in, const int* in_sizes, int n_in,
                              void* d_out, int out_size) {
    const float* inputs = (const float*)d_in[0];
    const void*  masks  = d_in[1];
    const float* emb    = (const float*)d_in[2];
    const float* wkey   = (const float*)d_in[3];
    float* out = (float*)d_out;
    (void)in_sizes; (void)n_in; (void)out_size;

    cudaFuncSetAttribute(k_keyproj, cudaFuncAttributeMaxDynamicSharedMemorySize, K1_SMEM_BYTES);
    cudaFuncSetAttribute(k_fused,   cudaFuncAttributeMaxDynamicSharedMemorySize, F_SMEM_BYTES);

    __half* d_xh;  cudaGetSymbolAddress((void**)&d_xh,  g_xh);
    __half* d_xth; cudaGetSymbolAddress((void**)&d_xth, g_xth);
    __half* d_eh;  cudaGetSymbolAddress((void**)&d_eh,  g_eh);
    __half* d_wh;  cudaGetSymbolAddress((void**)&d_wh,  g_wh);

    k_detect<<<1, 256>>>((const int*)masks);
    k_cvt<<<512, 256>>>((const float4*)inputs, (uint4*)d_xh, Bdim * Sdim * Hdim / 8);
    k_cvt<<<512, 256>>>((const float4*)emb,    (uint4*)d_eh, Ldim * Hdim / 8);
    k_cvt<<<256, 256>>>((const float4*)wkey,   (uint4*)d_wh, Hdim * Hdim / 8);
    k_trh<<<dim3(Hdim / 32, Sdim / 32, Bdim), dim3(32, 8)>>>(inputs, d_xth);
    k_keyproj<<<dim3(6, 32, 1), 256, K1_SMEM_BYTES>>>(d_xh, d_wh);
    k_fused<<<dim3(Ldim / 64, Bdim), 256, F_SMEM_BYTES>>>(d_eh, d_xth, masks, out);
}